// round 12
// baseline (speedup 1.0000x reference)
#include <cuda_runtime.h>
#include <cuda_bf16.h>
#include <cstdint>
#include <math.h>

#define BATCH 8
#define N2v 8192
#define N1v 2048
#define C1v 256
#define C2v 128
#define K1v 384
#define COv 256

#define NSPLIT 4
#define NCAND (N1v / NSPLIT)

#define BM 128
#define BN 128
#define KC 32
#define PADW 20                    // A row stride in u32
#define SBW 136                    // B row stride in u32
#define OF_AHI 0
#define OF_ALO 2560                // 128*20
#define OF_BHI 5120
#define OF_BLO (5120 + 16 * SBW)   // 7296
#define BUFU32 (OF_BLO + 16 * SBW) // 9472
#define NSTAGE 3
#define SM_BYTES (NSTAGE * BUFU32 * 4)   // 113664

// ---------------- scratch (static device globals; no allocation) ----------------
__device__ uint32_t g_y1h[(size_t)BATCH * COv * N2v / 2];   // y1 pair-packed bf16 hi
__device__ uint32_t g_y1l[(size_t)BATCH * COv * N2v / 2];   // y1 pair-packed bf16 lo
__device__ int   g_idx[BATCH * 3 * N2v];
__device__ float g_wgt[BATCH * 3 * N2v];
__device__ float g_pk[BATCH * NSPLIT * 3 * N2v];
__device__ int   g_pi[BATCH * NSPLIT * 3 * N2v];
__device__ float g_sc1[COv], g_sh1[COv], g_sc2[COv], g_sh2[COv];
__device__ float g_s1[COv], g_q1[COv], g_s2[COv], g_q2[COv];
__device__ __align__(16) __nv_bfloat16 g_ah1[COv * K1v], g_al1[COv * K1v];
__device__ __align__(16) __nv_bfloat16 g_ah2[COv * COv], g_al2[COv * COv];
__device__ uint32_t g_bh1[(size_t)BATCH * (K1v / 2) * N2v], g_bl1[(size_t)BATCH * (K1v / 2) * N2v];
__device__ uint32_t g_bh2[(size_t)BATCH * (COv / 2) * N2v], g_bl2[(size_t)BATCH * (COv / 2) * N2v];

__device__ __forceinline__ uint32_t s2u(const void* p) {
    uint32_t a;
    asm("{ .reg .u64 t; cvta.to.shared.u64 t, %1; cvt.u32.u64 %0, t; }" : "=r"(a) : "l"(p));
    return a;
}
__device__ __forceinline__ uint32_t pack_hi_lo(float v0, float v1, uint32_t& lop) {
    __nv_bfloat16 h0 = __float2bfloat16_rn(v0);
    __nv_bfloat16 h1 = __float2bfloat16_rn(v1);
    __nv_bfloat16 l0 = __float2bfloat16_rn(v0 - __bfloat162float(h0));
    __nv_bfloat16 l1 = __float2bfloat16_rn(v1 - __bfloat162float(h1));
    lop = (uint32_t)__bfloat16_as_ushort(l0) | ((uint32_t)__bfloat16_as_ushort(l1) << 16);
    return (uint32_t)__bfloat16_as_ushort(h0) | ((uint32_t)__bfloat16_as_ushort(h1) << 16);
}
__device__ __forceinline__ float2 unpk(uint32_t h, uint32_t l) {
    float2 r;
    r.x = __bfloat162float(__ushort_as_bfloat16((unsigned short)(h & 0xFFFF))) +
          __bfloat162float(__ushort_as_bfloat16((unsigned short)(l & 0xFFFF)));
    r.y = __bfloat162float(__ushort_as_bfloat16((unsigned short)(h >> 16))) +
          __bfloat162float(__ushort_as_bfloat16((unsigned short)(l >> 16)));
    return r;
}
__device__ __forceinline__ void mma_bf16(float* c, const uint32_t* a, uint32_t b0, uint32_t b1) {
    asm volatile(
        "mma.sync.aligned.m16n8k16.row.col.f32.bf16.bf16.f32 "
        "{%0,%1,%2,%3}, {%4,%5,%6,%7}, {%8,%9}, {%0,%1,%2,%3};"
        : "+f"(c[0]), "+f"(c[1]), "+f"(c[2]), "+f"(c[3])
        : "r"(a[0]), "r"(a[1]), "r"(a[2]), "r"(a[3]), "r"(b0), "r"(b1));
}
#define CP16(s, g) asm volatile("cp.async.cg.shared.global [%0], [%1], 16;" :: "r"(s), "l"(g))

// ---------------- bf16 3-product HMMA GEMM, 3-stage cp.async, 2 CTA/SM ----------
// PACKOUT=true: write pair-packed bf16 hi/lo planes (Ch/Cl) instead of fp32 C.
template <bool PACKOUT>
__global__ void __launch_bounds__(256, 2) tgemm_kernel(
    const __nv_bfloat16* __restrict__ Ah, const __nv_bfloat16* __restrict__ Al,
    const uint32_t* __restrict__ Bhp, const uint32_t* __restrict__ Blp,
    float* __restrict__ C, uint32_t* __restrict__ Ch, uint32_t* __restrict__ Cl,
    int K, const float* __restrict__ bias,
    float* __restrict__ gs, float* __restrict__ gq)
{
    extern __shared__ uint32_t smu[];
    const uint32_t sb = s2u(smu);
    const int tid = threadIdx.x;
    const int lane = tid & 31, wid = tid >> 5;
    const int wm = wid & 3, wn = wid >> 2;
    const int g = lane >> 2, tig = lane & 3;
    const int row0 = blockIdx.y * BM;
    const int n0 = blockIdx.x * BN;
    const int bz = blockIdx.z;

    const uint32_t* Bh = Bhp + (size_t)bz * (K / 2) * N2v;
    const uint32_t* Bl = Blp + (size_t)bz * (K / 2) * N2v;

    auto issue_stage = [&](int c) {
        const int buf = c % NSTAGE;
        const uint32_t base = sb + buf * (BUFU32 * 4);
        #pragma unroll
        for (int p = 0; p < 2; p++) {
            const __nv_bfloat16* Ag = p ? Al : Ah;
            #pragma unroll
            for (int i = 0; i < 2; i++) {
                int seg = tid + i * 256;
                int row = seg >> 2, off = seg & 3;
                uint32_t s = base + (p ? OF_ALO * 4 : 0) + row * (PADW * 4) + off * 16;
                const void* gp = Ag + (size_t)(row0 + row) * K + c * KC + off * 8;
                CP16(s, gp);
            }
        }
        #pragma unroll
        for (int p = 0; p < 2; p++) {
            const uint32_t* Bg = p ? Bl : Bh;
            #pragma unroll
            for (int i = 0; i < 2; i++) {
                int seg = tid + i * 256;
                int row = seg >> 5, col4 = seg & 31;
                uint32_t s = base + (p ? OF_BLO * 4 : OF_BHI * 4) + (row * SBW + col4 * 4) * 4;
                const void* gp = Bg + (size_t)(c * 16 + row) * N2v + n0 + col4 * 4;
                CP16(s, gp);
            }
        }
        asm volatile("cp.async.commit_group;" ::: "memory");
    };

    float acc[2][8][4];
    #pragma unroll
    for (int mt = 0; mt < 2; mt++)
        #pragma unroll
        for (int nt = 0; nt < 8; nt++)
            #pragma unroll
            for (int j = 0; j < 4; j++) acc[mt][nt][j] = 0.f;

    const int nc = K / KC;
    issue_stage(0);
    if (nc > 1) issue_stage(1);

    for (int c = 0; c < nc; c++) {
        if (c + 2 < nc) {
            issue_stage(c + 2);
            asm volatile("cp.async.wait_group 2;" ::: "memory");
        } else if (c + 1 < nc) {
            asm volatile("cp.async.wait_group 1;" ::: "memory");
        } else {
            asm volatile("cp.async.wait_group 0;" ::: "memory");
        }
        __syncthreads();

        const uint32_t* bb = smu + (c % NSTAGE) * BUFU32;
        #pragma unroll
        for (int ks = 0; ks < 2; ks++) {
            #pragma unroll
            for (int p = 0; p < 3; p++) {
                const int aoff = (p == 1) ? OF_ALO : OF_AHI;
                const int boff = (p == 2) ? OF_BLO : OF_BHI;
                uint32_t a[2][4];
                #pragma unroll
                for (int mt = 0; mt < 2; mt++) {
                    const uint32_t* pa = bb + aoff + (wm * 32 + mt * 16 + g) * PADW + ks * 8 + tig;
                    a[mt][0] = pa[0];
                    a[mt][1] = pa[8 * PADW];
                    a[mt][2] = pa[4];
                    a[mt][3] = pa[8 * PADW + 4];
                }
                const uint32_t* pb0 = bb + boff + (ks * 8 + tig) * SBW + wn * 64 + g;
                #pragma unroll
                for (int nt = 0; nt < 8; nt++) {
                    uint32_t b0 = pb0[nt * 8];
                    uint32_t b1 = pb0[nt * 8 + 4 * SBW];
                    mma_bf16(acc[0][nt], a[0], b0, b1);
                    mma_bf16(acc[1][nt], a[1], b0, b1);
                }
            }
        }
        __syncthreads();
    }

    // ---- epilogue: bias, store (fp32 or packed hi/lo), fused BN stats ----
    #pragma unroll
    for (int mt = 0; mt < 2; mt++) {
        #pragma unroll
        for (int h = 0; h < 2; h++) {
            const int rloc = row0 + wm * 32 + mt * 16 + g + h * 8;
            const float bs = bias[rloc];
            float s = 0.f, q = 0.f;
            if (PACKOUT) {
                uint32_t* ph = Ch + ((size_t)bz * COv + rloc) * (N2v / 2) + n0 / 2 + wn * 32 + tig;
                uint32_t* pl = Cl + ((size_t)bz * COv + rloc) * (N2v / 2) + n0 / 2 + wn * 32 + tig;
                #pragma unroll
                for (int nt = 0; nt < 8; nt++) {
                    float v0 = acc[mt][nt][2 * h] + bs;
                    float v1 = acc[mt][nt][2 * h + 1] + bs;
                    s += v0 + v1;
                    q = fmaf(v0, v0, fmaf(v1, v1, q));
                    uint32_t lo, hi = pack_hi_lo(v0, v1, lo);
                    ph[nt * 4] = hi;
                    pl[nt * 4] = lo;
                }
            } else {
                float* p = C + ((size_t)bz * COv + rloc) * (size_t)N2v + n0 + wn * 64 + tig * 2;
                #pragma unroll
                for (int nt = 0; nt < 8; nt++) {
                    float v0 = acc[mt][nt][2 * h] + bs;
                    float v1 = acc[mt][nt][2 * h + 1] + bs;
                    s += v0 + v1;
                    q = fmaf(v0, v0, fmaf(v1, v1, q));
                    *(float2*)(p + nt * 8) = make_float2(v0, v1);
                }
            }
            #pragma unroll
            for (int o = 1; o <= 2; o <<= 1) {
                s += __shfl_xor_sync(0xFFFFFFFFu, s, o);
                q += __shfl_xor_sync(0xFFFFFFFFu, q, o);
            }
            if (tig == 0) {
                atomicAdd(&gs[rloc], s);
                atomicAdd(&gq[rloc], q);
            }
        }
    }
}

// ---------------- 0) zero the stat accumulators ----------------
__global__ void zero_stats_kernel()
{
    const int t = threadIdx.x;
    g_s1[t] = 0.f; g_q1[t] = 0.f; g_s2[t] = 0.f; g_q2[t] = 0.f;
}

// ---------------- 1a) three_nn partials (verified) ----------------
__global__ void __launch_bounds__(256) knn3_part_kernel(
    const float* __restrict__ xyz2, const float* __restrict__ xyz1)
{
    __shared__ float4 sp[NCAND];
    const int b = blockIdx.y;
    const int z = blockIdx.z;
    const float* p1 = xyz1 + (size_t)b * 3 * N1v + z * NCAND;
    for (int j = threadIdx.x; j < NCAND; j += blockDim.x) {
        float x = p1[j], y = p1[N1v + j], zc = p1[2 * N1v + j];
        sp[j] = make_float4(x, y, zc, fmaf(x, x, fmaf(y, y, zc * zc)));
    }
    __syncthreads();

    const int n = blockIdx.x * blockDim.x + threadIdx.x;
    const float* p2 = xyz2 + (size_t)b * 3 * N2v;
    const float px = p2[n], py = p2[N2v + n], pz = p2[2 * N2v + n];
    const float ax = -2.f * px, ay = -2.f * py, az = -2.f * pz;

    float d0 = 3.4e38f, d1 = 3.4e38f, d2 = 3.4e38f;
    int i0 = 0, i1 = 0, i2 = 0;
    #pragma unroll 8
    for (int j = 0; j < NCAND; j++) {
        float4 q = sp[j];
        float d = fmaf(q.x, ax, fmaf(q.y, ay, fmaf(q.z, az, q.w)));
        if (d < d2) {
            if (d < d1) {
                d2 = d1; i2 = i1;
                if (d < d0) { d1 = d0; i1 = i0; d0 = d; i0 = j; }
                else        { d1 = d;  i1 = j; }
            } else { d2 = d; i2 = j; }
        }
    }
    const int jb = z * NCAND;
    const size_t base = ((size_t)(b * NSPLIT + z) * 3) * N2v + n;
    g_pk[base] = d0;            g_pi[base] = jb + i0;
    g_pk[base + N2v] = d1;      g_pi[base + N2v] = jb + i1;
    g_pk[base + 2 * N2v] = d2;  g_pi[base + 2 * N2v] = jb + i2;
}

// ---------------- 1b) merge partials -> top-3, exact dists, weights -------------
__global__ void __launch_bounds__(256) knn3_merge_kernel(
    const float* __restrict__ xyz2, const float* __restrict__ xyz1)
{
    const int gid = blockIdx.x * blockDim.x + threadIdx.x;
    const int b = gid >> 13, n = gid & (N2v - 1);

    float d0 = 3.4e38f, d1 = 3.4e38f, d2 = 3.4e38f;
    int i0 = 0, i1 = 0, i2 = 0;
    #pragma unroll
    for (int z = 0; z < NSPLIT; z++) {
        #pragma unroll
        for (int r = 0; r < 3; r++) {
            const size_t o = ((size_t)(b * NSPLIT + z) * 3 + r) * N2v + n;
            float d = g_pk[o];
            int ii = g_pi[o];
            if (d < d2) {
                if (d < d1) {
                    d2 = d1; i2 = i1;
                    if (d < d0) { d1 = d0; i1 = i0; d0 = d; i0 = ii; }
                    else        { d1 = d;  i1 = ii; }
                } else { d2 = d; i2 = ii; }
            }
        }
    }

    const float* p2 = xyz2 + (size_t)b * 3 * N2v;
    const float px = p2[n], py = p2[N2v + n], pz = p2[2 * N2v + n];
    const float* p1 = xyz1 + (size_t)b * 3 * N1v;
    auto exact = [&](int i) {
        float dx = px - p1[i], dy = py - p1[N1v + i], dz = pz - p1[2 * N1v + i];
        return fmaf(dx, dx, fmaf(dy, dy, dz * dz));
    };
    float e0 = fmaxf(exact(i0), 1e-10f);
    float e1 = fmaxf(exact(i1), 1e-10f);
    float e2 = fmaxf(exact(i2), 1e-10f);
    float w0 = 1.f / e0, w1 = 1.f / e1, w2 = 1.f / e2;
    float s = 1.f / (w0 + w1 + w2);
    const int base = b * 3 * N2v + n;
    g_idx[base] = i0; g_idx[base + N2v] = i1; g_idx[base + 2 * N2v] = i2;
    g_wgt[base] = w0 * s; g_wgt[base + N2v] = w1 * s; g_wgt[base + 2 * N2v] = w2 * s;
}

// ---------------- 2) gather + interpolation -> pair-packed B1 planes ------------
#define CPB 4
__global__ void __launch_bounds__(256) interp_kernel(const float* __restrict__ feat1)
{
    __shared__ float sf[CPB][N1v];
    const int b = blockIdx.y;
    const int c0 = blockIdx.x * CPB;
    const float* f = feat1 + ((size_t)b * C1v + c0) * N1v;
    for (int t = threadIdx.x; t < CPB * N1v; t += blockDim.x)
        (&sf[0][0])[t] = f[t];
    __syncthreads();

    const int base = b * 3 * N2v;
    const size_t o0 = ((size_t)b * (K1v / 2) + c0 / 2) * N2v;
    for (int n = threadIdx.x; n < N2v; n += blockDim.x) {
        const int i0 = g_idx[base + n];
        const int i1 = g_idx[base + N2v + n];
        const int i2 = g_idx[base + 2 * N2v + n];
        const float w0 = g_wgt[base + n];
        const float w1 = g_wgt[base + N2v + n];
        const float w2 = g_wgt[base + 2 * N2v + n];
        float v[CPB];
        #pragma unroll
        for (int c = 0; c < CPB; c++)
            v[c] = sf[c][i0] * w0 + sf[c][i1] * w1 + sf[c][i2] * w2;
        uint32_t l01, l23;
        uint32_t h01 = pack_hi_lo(v[0], v[1], l01);
        uint32_t h23 = pack_hi_lo(v[2], v[3], l23);
        g_bh1[o0 + n] = h01;        g_bl1[o0 + n] = l01;
        g_bh1[o0 + N2v + n] = h23;  g_bl1[o0 + N2v + n] = l23;
    }
}

// ---------------- 2b) feat2 -> pair-packed B1 planes ----------------------------
__global__ void __launch_bounds__(256) f2cvt_kernel(const float* __restrict__ f2)
{
    const size_t gid = (size_t)blockIdx.x * 256 + threadIdx.x;
    const int n4 = (int)(gid & 2047);
    const int i = (int)((gid >> 11) & 63);
    const int b = (int)(gid >> 17);
    const float* r0 = f2 + ((size_t)b * C2v + 2 * i) * N2v + n4 * 4;
    float4 a = *(const float4*)r0;
    float4 c = *(const float4*)(r0 + N2v);
    uint32_t h[4], l[4];
    h[0] = pack_hi_lo(a.x, c.x, l[0]);
    h[1] = pack_hi_lo(a.y, c.y, l[1]);
    h[2] = pack_hi_lo(a.z, c.z, l[2]);
    h[3] = pack_hi_lo(a.w, c.w, l[3]);
    const size_t o = ((size_t)b * (K1v / 2) + 128 + i) * N2v + n4 * 4;
    *(uint4*)(g_bh1 + o) = make_uint4(h[0], h[1], h[2], h[3]);
    *(uint4*)(g_bl1 + o) = make_uint4(l[0], l[1], l[2], l[3]);
}

// ---------------- weight split ----------------
__global__ void wcvt_kernel(const float* __restrict__ src,
                            __nv_bfloat16* __restrict__ dh, __nv_bfloat16* __restrict__ dl)
{
    const size_t i4 = (size_t)blockIdx.x * 256 + threadIdx.x;
    float4 v = ((const float4*)src)[i4];
    uint32_t l01, l23;
    uint32_t h01 = pack_hi_lo(v.x, v.y, l01);
    uint32_t h23 = pack_hi_lo(v.z, v.w, l23);
    *(uint2*)(dh + i4 * 4) = make_uint2(h01, h23);
    *(uint2*)(dl + i4 * 4) = make_uint2(l01, l23);
}

// ---------------- BN1+ReLU on packed y1 -> pair-packed B2 planes ----------------
__global__ void __launch_bounds__(256) bnsplit_kernel(
    const uint32_t* __restrict__ y1h, const uint32_t* __restrict__ y1l,
    const float* __restrict__ sc, const float* __restrict__ sh)
{
    const size_t gid = (size_t)blockIdx.x * 256 + threadIdx.x;
    const int n4 = (int)(gid & 2047);                 // group of 4 n (= 2 u32)
    const int i = (int)((gid >> 11) & 127);           // channel pair
    const int b = (int)(gid >> 18);
    const int c0 = 2 * i, c1 = 2 * i + 1;

    const size_t r0 = ((size_t)b * COv + c0) * (N2v / 2) + n4 * 2;
    const size_t r1 = ((size_t)b * COv + c1) * (N2v / 2) + n4 * 2;
    uint2 H0 = *(const uint2*)(y1h + r0);
    uint2 L0 = *(const uint2*)(y1l + r0);
    uint2 H1 = *(const uint2*)(y1h + r1);
    uint2 L1 = *(const uint2*)(y1l + r1);
    float2 a01 = unpk(H0.x, L0.x), a23 = unpk(H0.y, L0.y);
    float2 c01 = unpk(H1.x, L1.x), c23 = unpk(H1.y, L1.y);

    const float s0 = sc[c0], t0 = sh[c0], s1 = sc[c1], t1 = sh[c1];
    float a_[4] = { fmaxf(fmaf(a01.x, s0, t0), 0.f), fmaxf(fmaf(a01.y, s0, t0), 0.f),
                    fmaxf(fmaf(a23.x, s0, t0), 0.f), fmaxf(fmaf(a23.y, s0, t0), 0.f) };
    float c_[4] = { fmaxf(fmaf(c01.x, s1, t1), 0.f), fmaxf(fmaf(c01.y, s1, t1), 0.f),
                    fmaxf(fmaf(c23.x, s1, t1), 0.f), fmaxf(fmaf(c23.y, s1, t1), 0.f) };

    uint32_t h[4], l[4];
    #pragma unroll
    for (int j = 0; j < 4; j++)
        h[j] = pack_hi_lo(a_[j], c_[j], l[j]);
    const size_t o = ((size_t)b * (COv / 2) + i) * N2v + n4 * 4;
    *(uint4*)(g_bh2 + o) = make_uint4(h[0], h[1], h[2], h[3]);
    *(uint4*)(g_bl2 + o) = make_uint4(l[0], l[1], l[2], l[3]);
}

// ---------------- stats -> folded scale/shift ----------------
__global__ void bnfinalize_kernel(
    const float* __restrict__ gs, const float* __restrict__ gq,
    const float* __restrict__ gamma, const float* __restrict__ beta,
    float* __restrict__ sc, float* __restrict__ sh)
{
    const int c = threadIdx.x;
    const double cnt = (double)BATCH * (double)N2v;
    double mean = (double)gs[c] / cnt;
    double var = (double)gq[c] / cnt - mean * mean;
    float inv = (float)(1.0 / sqrt(var + 1e-3));
    float scale = gamma[c] * inv;
    sc[c] = scale;
    sh[c] = beta[c] - (float)mean * scale;
}

// ---------------- final BN+ReLU in place on d_out ----------------
__global__ void __launch_bounds__(256) bnapply_kernel(
    float* __restrict__ Y, const float* __restrict__ sc, const float* __restrict__ sh)
{
    const size_t i = ((size_t)blockIdx.x * blockDim.x + threadIdx.x) * 4;
    const int c = (int)((i >> 13) & (COv - 1));
    float4 v = *(float4*)(Y + i);
    const float s = sc[c], t = sh[c];
    v.x = fmaxf(fmaf(v.x, s, t), 0.f);
    v.y = fmaxf(fmaf(v.y, s, t), 0.f);
    v.z = fmaxf(fmaf(v.z, s, t), 0.f);
    v.w = fmaxf(fmaf(v.w, s, t), 0.f);
    *(float4*)(Y + i) = v;
}

// ---------------- launch ----------------
extern "C" void kernel_launch(void* const* d_in, const int* in_sizes, int n_in,
                              void* d_out, int out_size)
{
    const float* xyz2  = (const float*)d_in[0];
    const float* xyz1  = (const float*)d_in[1];
    const float* feat2 = (const float*)d_in[2];
    const float* feat1 = (const float*)d_in[3];
    const float* W1    = (const float*)d_in[4];
    const float* b1    = (const float*)d_in[5];
    const float* g1    = (const float*)d_in[6];
    const float* be1   = (const float*)d_in[7];
    const float* W2    = (const float*)d_in[8];
    const float* b2    = (const float*)d_in[9];
    const float* g2    = (const float*)d_in[10];
    const float* be2   = (const float*)d_in[11];
    float* out = (float*)d_out;

    float *sc1, *sh1, *sc2, *sh2, *s1, *q1, *s2, *q2;
    __nv_bfloat16 *ah1, *al1, *ah2, *al2;
    uint32_t *bh1, *bl1, *bh2, *bl2, *y1h, *y1l;
    cudaGetSymbolAddress((void**)&y1h, g_y1h);
    cudaGetSymbolAddress((void**)&y1l, g_y1l);
    cudaGetSymbolAddress((void**)&sc1, g_sc1);
    cudaGetSymbolAddress((void**)&sh1, g_sh1);
    cudaGetSymbolAddress((void**)&sc2, g_sc2);
    cudaGetSymbolAddress((void**)&sh2, g_sh2);
    cudaGetSymbolAddress((void**)&s1,  g_s1);
    cudaGetSymbolAddress((void**)&q1,  g_q1);
    cudaGetSymbolAddress((void**)&s2,  g_s2);
    cudaGetSymbolAddress((void**)&q2,  g_q2);
    cudaGetSymbolAddress((void**)&ah1, g_ah1);
    cudaGetSymbolAddress((void**)&al1, g_al1);
    cudaGetSymbolAddress((void**)&ah2, g_ah2);
    cudaGetSymbolAddress((void**)&al2, g_al2);
    cudaGetSymbolAddress((void**)&bh1, g_bh1);
    cudaGetSymbolAddress((void**)&bl1, g_bl1);
    cudaGetSymbolAddress((void**)&bh2, g_bh2);
    cudaGetSymbolAddress((void**)&bl2, g_bl2);

    cudaFuncSetAttribute(tgemm_kernel<true>,  cudaFuncAttributeMaxDynamicSharedMemorySize, SM_BYTES);
    cudaFuncSetAttribute(tgemm_kernel<false>, cudaFuncAttributeMaxDynamicSharedMemorySize, SM_BYTES);

    zero_stats_kernel<<<1, COv>>>();
    wcvt_kernel<<<(COv * K1v) / 1024, 256>>>(W1, ah1, al1);
    wcvt_kernel<<<(COv * COv) / 1024, 256>>>(W2, ah2, al2);
    knn3_part_kernel<<<dim3(N2v / 256, BATCH, NSPLIT), 256>>>(xyz2, xyz1);
    knn3_merge_kernel<<<(BATCH * N2v) / 256, 256>>>(xyz2, xyz1);
    interp_kernel<<<dim3(C1v / CPB, BATCH), 256>>>(feat1);
    f2cvt_kernel<<<((size_t)BATCH * (C2v / 2) * (N2v / 4)) / 256, 256>>>(feat2);
    // conv1 -> packed y1 planes + BN1 stats
    tgemm_kernel<true><<<dim3(N2v / BN, COv / BM, BATCH), 256, SM_BYTES>>>(
        ah1, al1, bh1, bl1, nullptr, y1h, y1l, K1v, b1, s1, q1);
    bnfinalize_kernel<<<1, COv>>>(s1, q1, g1, be1, sc1, sh1);
    bnsplit_kernel<<<((size_t)BATCH * (COv / 2) * (N2v / 4)) / 256, 256>>>(y1h, y1l, sc1, sh1);
    // conv2 -> fp32 out + BN2 stats
    tgemm_kernel<false><<<dim3(N2v / BN, COv / BM, BATCH), 256, SM_BYTES>>>(
        ah2, al2, bh2, bl2, out, nullptr, nullptr, COv, b2, s2, q2);
    bnfinalize_kernel<<<1, COv>>>(s2, q2, g2, be2, sc2, sh2);
    bnapply_kernel<<<((size_t)BATCH * COv * N2v) / 1024, 256>>>(out, sc2, sh2);
}

// round 13
// speedup vs baseline: 1.0007x; 1.0007x over previous
#include <cuda_runtime.h>
#include <cuda_bf16.h>
#include <cstdint>
#include <math.h>

#define BATCH 8
#define N2v 8192
#define N1v 2048
#define C1v 256
#define C2v 128
#define K1v 384
#define COv 256

#define NSPLIT 4
#define NCAND (N1v / NSPLIT)

#define BM 128
#define BN 128
#define KC 32
#define PADW 20                    // A row stride in u32
#define SBW 136                    // B row stride in u32
#define OF_AHI 0
#define OF_ALO 2560                // 128*20
#define OF_BHI 5120
#define OF_BLO (5120 + 16 * SBW)   // 7296
#define BUFU32 (OF_BLO + 16 * SBW) // 9472
#define NSTAGE 2
#define SM_BYTES (NSTAGE * BUFU32 * 4)   // 75776

// ---------------- scratch (static device globals; no allocation) ----------------
__device__ uint32_t g_y1h[(size_t)BATCH * COv * N2v / 2];   // y1 pair-packed bf16 hi
__device__ uint32_t g_y1l[(size_t)BATCH * COv * N2v / 2];   // y1 pair-packed bf16 lo
__device__ int   g_idx[BATCH * 3 * N2v];
__device__ float g_wgt[BATCH * 3 * N2v];
__device__ float g_pk[BATCH * NSPLIT * 3 * N2v];
__device__ int   g_pi[BATCH * NSPLIT * 3 * N2v];
__device__ float g_sc1[COv], g_sh1[COv], g_sc2[COv], g_sh2[COv];
__device__ float g_s1[COv], g_q1[COv], g_s2[COv], g_q2[COv];
__device__ __align__(16) __nv_bfloat16 g_ah1[COv * K1v], g_al1[COv * K1v];
__device__ __align__(16) __nv_bfloat16 g_ah2[COv * COv], g_al2[COv * COv];
__device__ uint32_t g_bh1[(size_t)BATCH * (K1v / 2) * N2v], g_bl1[(size_t)BATCH * (K1v / 2) * N2v];
__device__ uint32_t g_bh2[(size_t)BATCH * (COv / 2) * N2v], g_bl2[(size_t)BATCH * (COv / 2) * N2v];

__device__ __forceinline__ uint32_t s2u(const void* p) {
    uint32_t a;
    asm("{ .reg .u64 t; cvta.to.shared.u64 t, %1; cvt.u32.u64 %0, t; }" : "=r"(a) : "l"(p));
    return a;
}
__device__ __forceinline__ uint32_t pack_hi_lo(float v0, float v1, uint32_t& lop) {
    __nv_bfloat16 h0 = __float2bfloat16_rn(v0);
    __nv_bfloat16 h1 = __float2bfloat16_rn(v1);
    __nv_bfloat16 l0 = __float2bfloat16_rn(v0 - __bfloat162float(h0));
    __nv_bfloat16 l1 = __float2bfloat16_rn(v1 - __bfloat162float(h1));
    lop = (uint32_t)__bfloat16_as_ushort(l0) | ((uint32_t)__bfloat16_as_ushort(l1) << 16);
    return (uint32_t)__bfloat16_as_ushort(h0) | ((uint32_t)__bfloat16_as_ushort(h1) << 16);
}
__device__ __forceinline__ float2 unpk(uint32_t h, uint32_t l) {
    float2 r;
    r.x = __bfloat162float(__ushort_as_bfloat16((unsigned short)(h & 0xFFFF))) +
          __bfloat162float(__ushort_as_bfloat16((unsigned short)(l & 0xFFFF)));
    r.y = __bfloat162float(__ushort_as_bfloat16((unsigned short)(h >> 16))) +
          __bfloat162float(__ushort_as_bfloat16((unsigned short)(l >> 16)));
    return r;
}
__device__ __forceinline__ void mma_bf16(float* c, const uint32_t* a, uint32_t b0, uint32_t b1) {
    asm volatile(
        "mma.sync.aligned.m16n8k16.row.col.f32.bf16.bf16.f32 "
        "{%0,%1,%2,%3}, {%4,%5,%6,%7}, {%8,%9}, {%0,%1,%2,%3};"
        : "+f"(c[0]), "+f"(c[1]), "+f"(c[2]), "+f"(c[3])
        : "r"(a[0]), "r"(a[1]), "r"(a[2]), "r"(a[3]), "r"(b0), "r"(b1));
}
#define CP16(s, g) asm volatile("cp.async.cg.shared.global [%0], [%1], 16;" :: "r"(s), "l"(g))

// ---------------- bf16 3-product HMMA GEMM, 2-stage cp.async, 2 CTA/SM ----------
// PACKOUT=true: write pair-packed bf16 hi/lo planes (Ch/Cl) instead of fp32 C.
template <bool PACKOUT>
__global__ void __launch_bounds__(256, 2) tgemm_kernel(
    const __nv_bfloat16* __restrict__ Ah, const __nv_bfloat16* __restrict__ Al,
    const uint32_t* __restrict__ Bhp, const uint32_t* __restrict__ Blp,
    float* __restrict__ C, uint32_t* __restrict__ Ch, uint32_t* __restrict__ Cl,
    int K, const float* __restrict__ bias,
    float* __restrict__ gs, float* __restrict__ gq)
{
    extern __shared__ uint32_t smu[];
    const uint32_t sb = s2u(smu);
    const int tid = threadIdx.x;
    const int lane = tid & 31, wid = tid >> 5;
    const int wm = wid & 3, wn = wid >> 2;
    const int g = lane >> 2, tig = lane & 3;
    const int row0 = blockIdx.y * BM;
    const int n0 = blockIdx.x * BN;
    const int bz = blockIdx.z;

    const uint32_t* Bh = Bhp + (size_t)bz * (K / 2) * N2v;
    const uint32_t* Bl = Blp + (size_t)bz * (K / 2) * N2v;

    auto issue_stage = [&](int c) {
        const int buf = c & 1;
        const uint32_t base = sb + buf * (BUFU32 * 4);
        #pragma unroll
        for (int p = 0; p < 2; p++) {
            const __nv_bfloat16* Ag = p ? Al : Ah;
            #pragma unroll
            for (int i = 0; i < 2; i++) {
                int seg = tid + i * 256;
                int row = seg >> 2, off = seg & 3;
                uint32_t s = base + (p ? OF_ALO * 4 : 0) + row * (PADW * 4) + off * 16;
                const void* gp = Ag + (size_t)(row0 + row) * K + c * KC + off * 8;
                CP16(s, gp);
            }
        }
        #pragma unroll
        for (int p = 0; p < 2; p++) {
            const uint32_t* Bg = p ? Bl : Bh;
            #pragma unroll
            for (int i = 0; i < 2; i++) {
                int seg = tid + i * 256;
                int row = seg >> 5, col4 = seg & 31;
                uint32_t s = base + (p ? OF_BLO * 4 : OF_BHI * 4) + (row * SBW + col4 * 4) * 4;
                const void* gp = Bg + (size_t)(c * 16 + row) * N2v + n0 + col4 * 4;
                CP16(s, gp);
            }
        }
        asm volatile("cp.async.commit_group;" ::: "memory");
    };

    float acc[2][8][4];
    #pragma unroll
    for (int mt = 0; mt < 2; mt++)
        #pragma unroll
        for (int nt = 0; nt < 8; nt++)
            #pragma unroll
            for (int j = 0; j < 4; j++) acc[mt][nt][j] = 0.f;

    const int nc = K / KC;
    issue_stage(0);

    for (int c = 0; c < nc; c++) {
        if (c + 1 < nc) {
            issue_stage(c + 1);
            asm volatile("cp.async.wait_group 1;" ::: "memory");
        } else {
            asm volatile("cp.async.wait_group 0;" ::: "memory");
        }
        __syncthreads();

        const uint32_t* bb = smu + (c & 1) * BUFU32;
        #pragma unroll
        for (int ks = 0; ks < 2; ks++) {
            #pragma unroll
            for (int p = 0; p < 3; p++) {
                const int aoff = (p == 1) ? OF_ALO : OF_AHI;
                const int boff = (p == 2) ? OF_BLO : OF_BHI;
                uint32_t a[2][4];
                #pragma unroll
                for (int mt = 0; mt < 2; mt++) {
                    const uint32_t* pa = bb + aoff + (wm * 32 + mt * 16 + g) * PADW + ks * 8 + tig;
                    a[mt][0] = pa[0];
                    a[mt][1] = pa[8 * PADW];
                    a[mt][2] = pa[4];
                    a[mt][3] = pa[8 * PADW + 4];
                }
                const uint32_t* pb0 = bb + boff + (ks * 8 + tig) * SBW + wn * 64 + g;
                #pragma unroll
                for (int nt = 0; nt < 8; nt++) {
                    uint32_t b0 = pb0[nt * 8];
                    uint32_t b1 = pb0[nt * 8 + 4 * SBW];
                    mma_bf16(acc[0][nt], a[0], b0, b1);
                    mma_bf16(acc[1][nt], a[1], b0, b1);
                }
            }
        }
        __syncthreads();
    }

    // ---- epilogue: bias, store (fp32 or packed hi/lo), fused BN stats ----
    #pragma unroll
    for (int mt = 0; mt < 2; mt++) {
        #pragma unroll
        for (int h = 0; h < 2; h++) {
            const int rloc = row0 + wm * 32 + mt * 16 + g + h * 8;
            const float bs = bias[rloc];
            float s = 0.f, q = 0.f;
            if (PACKOUT) {
                uint32_t* ph = Ch + ((size_t)bz * COv + rloc) * (N2v / 2) + n0 / 2 + wn * 32 + tig;
                uint32_t* pl = Cl + ((size_t)bz * COv + rloc) * (N2v / 2) + n0 / 2 + wn * 32 + tig;
                #pragma unroll
                for (int nt = 0; nt < 8; nt++) {
                    float v0 = acc[mt][nt][2 * h] + bs;
                    float v1 = acc[mt][nt][2 * h + 1] + bs;
                    s += v0 + v1;
                    q = fmaf(v0, v0, fmaf(v1, v1, q));
                    uint32_t lo, hi = pack_hi_lo(v0, v1, lo);
                    ph[nt * 4] = hi;
                    pl[nt * 4] = lo;
                }
            } else {
                float* p = C + ((size_t)bz * COv + rloc) * (size_t)N2v + n0 + wn * 64 + tig * 2;
                #pragma unroll
                for (int nt = 0; nt < 8; nt++) {
                    float v0 = acc[mt][nt][2 * h] + bs;
                    float v1 = acc[mt][nt][2 * h + 1] + bs;
                    s += v0 + v1;
                    q = fmaf(v0, v0, fmaf(v1, v1, q));
                    *(float2*)(p + nt * 8) = make_float2(v0, v1);
                }
            }
            #pragma unroll
            for (int o = 1; o <= 2; o <<= 1) {
                s += __shfl_xor_sync(0xFFFFFFFFu, s, o);
                q += __shfl_xor_sync(0xFFFFFFFFu, q, o);
            }
            if (tig == 0) {
                atomicAdd(&gs[rloc], s);
                atomicAdd(&gq[rloc], q);
            }
        }
    }
}

// ---------------- 0) zero the stat accumulators ----------------
__global__ void zero_stats_kernel()
{
    const int t = threadIdx.x;
    g_s1[t] = 0.f; g_q1[t] = 0.f; g_s2[t] = 0.f; g_q2[t] = 0.f;
}

// ---------------- 1a) three_nn partials (verified) ----------------
__global__ void __launch_bounds__(256) knn3_part_kernel(
    const float* __restrict__ xyz2, const float* __restrict__ xyz1)
{
    __shared__ float4 sp[NCAND];
    const int b = blockIdx.y;
    const int z = blockIdx.z;
    const float* p1 = xyz1 + (size_t)b * 3 * N1v + z * NCAND;
    for (int j = threadIdx.x; j < NCAND; j += blockDim.x) {
        float x = p1[j], y = p1[N1v + j], zc = p1[2 * N1v + j];
        sp[j] = make_float4(x, y, zc, fmaf(x, x, fmaf(y, y, zc * zc)));
    }
    __syncthreads();

    const int n = blockIdx.x * blockDim.x + threadIdx.x;
    const float* p2 = xyz2 + (size_t)b * 3 * N2v;
    const float px = p2[n], py = p2[N2v + n], pz = p2[2 * N2v + n];
    const float ax = -2.f * px, ay = -2.f * py, az = -2.f * pz;

    float d0 = 3.4e38f, d1 = 3.4e38f, d2 = 3.4e38f;
    int i0 = 0, i1 = 0, i2 = 0;
    #pragma unroll 8
    for (int j = 0; j < NCAND; j++) {
        float4 q = sp[j];
        float d = fmaf(q.x, ax, fmaf(q.y, ay, fmaf(q.z, az, q.w)));
        if (d < d2) {
            if (d < d1) {
                d2 = d1; i2 = i1;
                if (d < d0) { d1 = d0; i1 = i0; d0 = d; i0 = j; }
                else        { d1 = d;  i1 = j; }
            } else { d2 = d; i2 = j; }
        }
    }
    const int jb = z * NCAND;
    const size_t base = ((size_t)(b * NSPLIT + z) * 3) * N2v + n;
    g_pk[base] = d0;            g_pi[base] = jb + i0;
    g_pk[base + N2v] = d1;      g_pi[base + N2v] = jb + i1;
    g_pk[base + 2 * N2v] = d2;  g_pi[base + 2 * N2v] = jb + i2;
}

// ---------------- 1b) merge partials -> top-3, exact dists, weights -------------
__global__ void __launch_bounds__(256) knn3_merge_kernel(
    const float* __restrict__ xyz2, const float* __restrict__ xyz1)
{
    const int gid = blockIdx.x * blockDim.x + threadIdx.x;
    const int b = gid >> 13, n = gid & (N2v - 1);

    float d0 = 3.4e38f, d1 = 3.4e38f, d2 = 3.4e38f;
    int i0 = 0, i1 = 0, i2 = 0;
    #pragma unroll
    for (int z = 0; z < NSPLIT; z++) {
        #pragma unroll
        for (int r = 0; r < 3; r++) {
            const size_t o = ((size_t)(b * NSPLIT + z) * 3 + r) * N2v + n;
            float d = g_pk[o];
            int ii = g_pi[o];
            if (d < d2) {
                if (d < d1) {
                    d2 = d1; i2 = i1;
                    if (d < d0) { d1 = d0; i1 = i0; d0 = d; i0 = ii; }
                    else        { d1 = d;  i1 = ii; }
                } else { d2 = d; i2 = ii; }
            }
        }
    }

    const float* p2 = xyz2 + (size_t)b * 3 * N2v;
    const float px = p2[n], py = p2[N2v + n], pz = p2[2 * N2v + n];
    const float* p1 = xyz1 + (size_t)b * 3 * N1v;
    auto exact = [&](int i) {
        float dx = px - p1[i], dy = py - p1[N1v + i], dz = pz - p1[2 * N1v + i];
        return fmaf(dx, dx, fmaf(dy, dy, dz * dz));
    };
    float e0 = fmaxf(exact(i0), 1e-10f);
    float e1 = fmaxf(exact(i1), 1e-10f);
    float e2 = fmaxf(exact(i2), 1e-10f);
    float w0 = 1.f / e0, w1 = 1.f / e1, w2 = 1.f / e2;
    float s = 1.f / (w0 + w1 + w2);
    const int base = b * 3 * N2v + n;
    g_idx[base] = i0; g_idx[base + N2v] = i1; g_idx[base + 2 * N2v] = i2;
    g_wgt[base] = w0 * s; g_wgt[base + N2v] = w1 * s; g_wgt[base + 2 * N2v] = w2 * s;
}

// ---------------- 2) gather + interpolation -> pair-packed B1 planes ------------
#define CPB 4
__global__ void __launch_bounds__(256) interp_kernel(const float* __restrict__ feat1)
{
    __shared__ float sf[CPB][N1v];
    const int b = blockIdx.y;
    const int c0 = blockIdx.x * CPB;
    const float* f = feat1 + ((size_t)b * C1v + c0) * N1v;
    for (int t = threadIdx.x; t < CPB * N1v; t += blockDim.x)
        (&sf[0][0])[t] = f[t];
    __syncthreads();

    const int base = b * 3 * N2v;
    const size_t o0 = ((size_t)b * (K1v / 2) + c0 / 2) * N2v;
    for (int n = threadIdx.x; n < N2v; n += blockDim.x) {
        const int i0 = g_idx[base + n];
        const int i1 = g_idx[base + N2v + n];
        const int i2 = g_idx[base + 2 * N2v + n];
        const float w0 = g_wgt[base + n];
        const float w1 = g_wgt[base + N2v + n];
        const float w2 = g_wgt[base + 2 * N2v + n];
        float v[CPB];
        #pragma unroll
        for (int c = 0; c < CPB; c++)
            v[c] = sf[c][i0] * w0 + sf[c][i1] * w1 + sf[c][i2] * w2;
        uint32_t l01, l23;
        uint32_t h01 = pack_hi_lo(v[0], v[1], l01);
        uint32_t h23 = pack_hi_lo(v[2], v[3], l23);
        g_bh1[o0 + n] = h01;        g_bl1[o0 + n] = l01;
        g_bh1[o0 + N2v + n] = h23;  g_bl1[o0 + N2v + n] = l23;
    }
}

// ---------------- 2b) feat2 -> pair-packed B1 planes ----------------------------
__global__ void __launch_bounds__(256) f2cvt_kernel(const float* __restrict__ f2)
{
    const size_t gid = (size_t)blockIdx.x * 256 + threadIdx.x;
    const int n4 = (int)(gid & 2047);
    const int i = (int)((gid >> 11) & 63);
    const int b = (int)(gid >> 17);
    const float* r0 = f2 + ((size_t)b * C2v + 2 * i) * N2v + n4 * 4;
    float4 a = *(const float4*)r0;
    float4 c = *(const float4*)(r0 + N2v);
    uint32_t h[4], l[4];
    h[0] = pack_hi_lo(a.x, c.x, l[0]);
    h[1] = pack_hi_lo(a.y, c.y, l[1]);
    h[2] = pack_hi_lo(a.z, c.z, l[2]);
    h[3] = pack_hi_lo(a.w, c.w, l[3]);
    const size_t o = ((size_t)b * (K1v / 2) + 128 + i) * N2v + n4 * 4;
    *(uint4*)(g_bh1 + o) = make_uint4(h[0], h[1], h[2], h[3]);
    *(uint4*)(g_bl1 + o) = make_uint4(l[0], l[1], l[2], l[3]);
}

// ---------------- weight split ----------------
__global__ void wcvt_kernel(const float* __restrict__ src,
                            __nv_bfloat16* __restrict__ dh, __nv_bfloat16* __restrict__ dl)
{
    const size_t i4 = (size_t)blockIdx.x * 256 + threadIdx.x;
    float4 v = ((const float4*)src)[i4];
    uint32_t l01, l23;
    uint32_t h01 = pack_hi_lo(v.x, v.y, l01);
    uint32_t h23 = pack_hi_lo(v.z, v.w, l23);
    *(uint2*)(dh + i4 * 4) = make_uint2(h01, h23);
    *(uint2*)(dl + i4 * 4) = make_uint2(l01, l23);
}

// ---------------- BN1+ReLU on packed y1 -> pair-packed B2 planes ----------------
__global__ void __launch_bounds__(256) bnsplit_kernel(
    const uint32_t* __restrict__ y1h, const uint32_t* __restrict__ y1l,
    const float* __restrict__ sc, const float* __restrict__ sh)
{
    const size_t gid = (size_t)blockIdx.x * 256 + threadIdx.x;
    const int n4 = (int)(gid & 2047);                 // group of 4 n (= 2 u32)
    const int i = (int)((gid >> 11) & 127);           // channel pair
    const int b = (int)(gid >> 18);
    const int c0 = 2 * i, c1 = 2 * i + 1;

    const size_t r0 = ((size_t)b * COv + c0) * (N2v / 2) + n4 * 2;
    const size_t r1 = ((size_t)b * COv + c1) * (N2v / 2) + n4 * 2;
    uint2 H0 = *(const uint2*)(y1h + r0);
    uint2 L0 = *(const uint2*)(y1l + r0);
    uint2 H1 = *(const uint2*)(y1h + r1);
    uint2 L1 = *(const uint2*)(y1l + r1);
    float2 a01 = unpk(H0.x, L0.x), a23 = unpk(H0.y, L0.y);
    float2 c01 = unpk(H1.x, L1.x), c23 = unpk(H1.y, L1.y);

    const float s0 = sc[c0], t0 = sh[c0], s1 = sc[c1], t1 = sh[c1];
    float a_[4] = { fmaxf(fmaf(a01.x, s0, t0), 0.f), fmaxf(fmaf(a01.y, s0, t0), 0.f),
                    fmaxf(fmaf(a23.x, s0, t0), 0.f), fmaxf(fmaf(a23.y, s0, t0), 0.f) };
    float c_[4] = { fmaxf(fmaf(c01.x, s1, t1), 0.f), fmaxf(fmaf(c01.y, s1, t1), 0.f),
                    fmaxf(fmaf(c23.x, s1, t1), 0.f), fmaxf(fmaf(c23.y, s1, t1), 0.f) };

    uint32_t h[4], l[4];
    #pragma unroll
    for (int j = 0; j < 4; j++)
        h[j] = pack_hi_lo(a_[j], c_[j], l[j]);
    const size_t o = ((size_t)b * (COv / 2) + i) * N2v + n4 * 4;
    *(uint4*)(g_bh2 + o) = make_uint4(h[0], h[1], h[2], h[3]);
    *(uint4*)(g_bl2 + o) = make_uint4(l[0], l[1], l[2], l[3]);
}

// ---------------- stats -> folded scale/shift ----------------
__global__ void bnfinalize_kernel(
    const float* __restrict__ gs, const float* __restrict__ gq,
    const float* __restrict__ gamma, const float* __restrict__ beta,
    float* __restrict__ sc, float* __restrict__ sh)
{
    const int c = threadIdx.x;
    const double cnt = (double)BATCH * (double)N2v;
    double mean = (double)gs[c] / cnt;
    double var = (double)gq[c] / cnt - mean * mean;
    float inv = (float)(1.0 / sqrt(var + 1e-3));
    float scale = gamma[c] * inv;
    sc[c] = scale;
    sh[c] = beta[c] - (float)mean * scale;
}

// ---------------- final BN+ReLU in place on d_out ----------------
__global__ void __launch_bounds__(256) bnapply_kernel(
    float* __restrict__ Y, const float* __restrict__ sc, const float* __restrict__ sh)
{
    const size_t i = ((size_t)blockIdx.x * blockDim.x + threadIdx.x) * 4;
    const int c = (int)((i >> 13) & (COv - 1));
    float4 v = *(float4*)(Y + i);
    const float s = sc[c], t = sh[c];
    v.x = fmaxf(fmaf(v.x, s, t), 0.f);
    v.y = fmaxf(fmaf(v.y, s, t), 0.f);
    v.z = fmaxf(fmaf(v.z, s, t), 0.f);
    v.w = fmaxf(fmaf(v.w, s, t), 0.f);
    *(float4*)(Y + i) = v;
}

// ---------------- launch ----------------
extern "C" void kernel_launch(void* const* d_in, const int* in_sizes, int n_in,
                              void* d_out, int out_size)
{
    const float* xyz2  = (const float*)d_in[0];
    const float* xyz1  = (const float*)d_in[1];
    const float* feat2 = (const float*)d_in[2];
    const float* feat1 = (const float*)d_in[3];
    const float* W1    = (const float*)d_in[4];
    const float* b1    = (const float*)d_in[5];
    const float* g1    = (const float*)d_in[6];
    const float* be1   = (const float*)d_in[7];
    const float* W2    = (const float*)d_in[8];
    const float* b2    = (const float*)d_in[9];
    const float* g2    = (const float*)d_in[10];
    const float* be2   = (const float*)d_in[11];
    float* out = (float*)d_out;

    float *sc1, *sh1, *sc2, *sh2, *s1, *q1, *s2, *q2;
    __nv_bfloat16 *ah1, *al1, *ah2, *al2;
    uint32_t *bh1, *bl1, *bh2, *bl2, *y1h, *y1l;
    cudaGetSymbolAddress((void**)&y1h, g_y1h);
    cudaGetSymbolAddress((void**)&y1l, g_y1l);
    cudaGetSymbolAddress((void**)&sc1, g_sc1);
    cudaGetSymbolAddress((void**)&sh1, g_sh1);
    cudaGetSymbolAddress((void**)&sc2, g_sc2);
    cudaGetSymbolAddress((void**)&sh2, g_sh2);
    cudaGetSymbolAddress((void**)&s1,  g_s1);
    cudaGetSymbolAddress((void**)&q1,  g_q1);
    cudaGetSymbolAddress((void**)&s2,  g_s2);
    cudaGetSymbolAddress((void**)&q2,  g_q2);
    cudaGetSymbolAddress((void**)&ah1, g_ah1);
    cudaGetSymbolAddress((void**)&al1, g_al1);
    cudaGetSymbolAddress((void**)&ah2, g_ah2);
    cudaGetSymbolAddress((void**)&al2, g_al2);
    cudaGetSymbolAddress((void**)&bh1, g_bh1);
    cudaGetSymbolAddress((void**)&bl1, g_bl1);
    cudaGetSymbolAddress((void**)&bh2, g_bh2);
    cudaGetSymbolAddress((void**)&bl2, g_bl2);

    cudaFuncSetAttribute(tgemm_kernel<true>,  cudaFuncAttributeMaxDynamicSharedMemorySize, SM_BYTES);
    cudaFuncSetAttribute(tgemm_kernel<false>, cudaFuncAttributeMaxDynamicSharedMemorySize, SM_BYTES);

    zero_stats_kernel<<<1, COv>>>();
    wcvt_kernel<<<(COv * K1v) / 1024, 256>>>(W1, ah1, al1);
    wcvt_kernel<<<(COv * COv) / 1024, 256>>>(W2, ah2, al2);
    knn3_part_kernel<<<dim3(N2v / 256, BATCH, NSPLIT), 256>>>(xyz2, xyz1);
    knn3_merge_kernel<<<(BATCH * N2v) / 256, 256>>>(xyz2, xyz1);
    interp_kernel<<<dim3(C1v / CPB, BATCH), 256>>>(feat1);
    f2cvt_kernel<<<((size_t)BATCH * (C2v / 2) * (N2v / 4)) / 256, 256>>>(feat2);
    // conv1 -> packed y1 planes + BN1 stats
    tgemm_kernel<true><<<dim3(N2v / BN, COv / BM, BATCH), 256, SM_BYTES>>>(
        ah1, al1, bh1, bl1, nullptr, y1h, y1l, K1v, b1, s1, q1);
    bnfinalize_kernel<<<1, COv>>>(s1, q1, g1, be1, sc1, sh1);
    bnsplit_kernel<<<((size_t)BATCH * (COv / 2) * (N2v / 4)) / 256, 256>>>(y1h, y1l, sc1, sh1);
    // conv2 -> fp32 out + BN2 stats
    tgemm_kernel<false><<<dim3(N2v / BN, COv / BM, BATCH), 256, SM_BYTES>>>(
        ah2, al2, bh2, bl2, out, nullptr, nullptr, COv, b2, s2, q2);
    bnfinalize_kernel<<<1, COv>>>(s2, q2, g2, be2, sc2, sh2);
    bnapply_kernel<<<((size_t)BATCH * COv * N2v) / 1024, 256>>>(out, sc2, sh2);
}

// round 14
// speedup vs baseline: 1.0060x; 1.0054x over previous
#include <cuda_runtime.h>
#include <cuda_bf16.h>
#include <cstdint>
#include <math.h>

#define BATCH 8
#define N2v 8192
#define N1v 2048
#define C1v 256
#define C2v 128
#define K1v 384
#define COv 256

#define NSPLIT 8
#define NCAND (N1v / NSPLIT)      // 256 candidates per partition
#define QPT 2                     // queries per thread in knn part

#define BM 128
#define BN 128
#define KC 32
#define PADW 20                    // A row stride in u32
#define SBW 136                    // B row stride in u32
#define OF_AHI 0
#define OF_ALO 2560                // 128*20
#define OF_BHI 5120
#define OF_BLO (5120 + 16 * SBW)   // 7296
#define BUFU32 (OF_BLO + 16 * SBW) // 9472
#define SM_BYTES (2 * BUFU32 * 4)  // 75776

// ---------------- scratch (static device globals; no allocation) ----------------
__device__ float g_y1[(size_t)BATCH * COv * N2v];
__device__ int   g_idx[BATCH * 3 * N2v];
__device__ float g_wgt[BATCH * 3 * N2v];
__device__ float g_pk[BATCH * NSPLIT * 3 * N2v];
__device__ int   g_pi[BATCH * NSPLIT * 3 * N2v];
__device__ float g_sc1[COv], g_sh1[COv], g_sc2[COv], g_sh2[COv];
__device__ float g_s1[COv], g_q1[COv], g_s2[COv], g_q2[COv];
__device__ __align__(16) __nv_bfloat16 g_ah1[COv * K1v], g_al1[COv * K1v];
__device__ __align__(16) __nv_bfloat16 g_ah2[COv * COv], g_al2[COv * COv];
__device__ uint32_t g_bh1[(size_t)BATCH * (K1v / 2) * N2v], g_bl1[(size_t)BATCH * (K1v / 2) * N2v];
__device__ uint32_t g_bh2[(size_t)BATCH * (COv / 2) * N2v], g_bl2[(size_t)BATCH * (COv / 2) * N2v];

__device__ __forceinline__ uint32_t s2u(const void* p) {
    uint32_t a;
    asm("{ .reg .u64 t; cvta.to.shared.u64 t, %1; cvt.u32.u64 %0, t; }" : "=r"(a) : "l"(p));
    return a;
}
__device__ __forceinline__ uint32_t pack_hi_lo(float v0, float v1, uint32_t& lop) {
    __nv_bfloat16 h0 = __float2bfloat16_rn(v0);
    __nv_bfloat16 h1 = __float2bfloat16_rn(v1);
    __nv_bfloat16 l0 = __float2bfloat16_rn(v0 - __bfloat162float(h0));
    __nv_bfloat16 l1 = __float2bfloat16_rn(v1 - __bfloat162float(h1));
    lop = (uint32_t)__bfloat16_as_ushort(l0) | ((uint32_t)__bfloat16_as_ushort(l1) << 16);
    return (uint32_t)__bfloat16_as_ushort(h0) | ((uint32_t)__bfloat16_as_ushort(h1) << 16);
}
__device__ __forceinline__ void mma_bf16(float* c, const uint32_t* a, uint32_t b0, uint32_t b1) {
    asm volatile(
        "mma.sync.aligned.m16n8k16.row.col.f32.bf16.bf16.f32 "
        "{%0,%1,%2,%3}, {%4,%5,%6,%7}, {%8,%9}, {%0,%1,%2,%3};"
        : "+f"(c[0]), "+f"(c[1]), "+f"(c[2]), "+f"(c[3])
        : "r"(a[0]), "r"(a[1]), "r"(a[2]), "r"(a[3]), "r"(b0), "r"(b1));
}
#define CP16(s, g) asm volatile("cp.async.cg.shared.global [%0], [%1], 16;" :: "r"(s), "l"(g))

// ---------------- bf16 3-product HMMA GEMM, 2-stage cp.async, 2 CTA/SM ----------
// (round-11 verified configuration)
__global__ void __launch_bounds__(256, 2) tgemm_kernel(
    const __nv_bfloat16* __restrict__ Ah, const __nv_bfloat16* __restrict__ Al,
    const uint32_t* __restrict__ Bhp, const uint32_t* __restrict__ Blp,
    float* __restrict__ C, int K,
    const float* __restrict__ bias,
    float* __restrict__ gs, float* __restrict__ gq)
{
    extern __shared__ uint32_t smu[];
    const uint32_t sb = s2u(smu);
    const int tid = threadIdx.x;
    const int lane = tid & 31, wid = tid >> 5;
    const int wm = wid & 3, wn = wid >> 2;
    const int g = lane >> 2, tig = lane & 3;
    const int row0 = blockIdx.y * BM;
    const int n0 = blockIdx.x * BN;
    const int bz = blockIdx.z;

    const uint32_t* Bh = Bhp + (size_t)bz * (K / 2) * N2v;
    const uint32_t* Bl = Blp + (size_t)bz * (K / 2) * N2v;

    auto issue_stage = [&](int c) {
        const int buf = c & 1;
        const uint32_t base = sb + buf * (BUFU32 * 4);
        #pragma unroll
        for (int p = 0; p < 2; p++) {
            const __nv_bfloat16* Ag = p ? Al : Ah;
            #pragma unroll
            for (int i = 0; i < 2; i++) {
                int seg = tid + i * 256;
                int row = seg >> 2, off = seg & 3;
                uint32_t s = base + (p ? OF_ALO * 4 : 0) + row * (PADW * 4) + off * 16;
                const void* gp = Ag + (size_t)(row0 + row) * K + c * KC + off * 8;
                CP16(s, gp);
            }
        }
        #pragma unroll
        for (int p = 0; p < 2; p++) {
            const uint32_t* Bg = p ? Bl : Bh;
            #pragma unroll
            for (int i = 0; i < 2; i++) {
                int seg = tid + i * 256;
                int row = seg >> 5, col4 = seg & 31;
                uint32_t s = base + (p ? OF_BLO * 4 : OF_BHI * 4) + (row * SBW + col4 * 4) * 4;
                const void* gp = Bg + (size_t)(c * 16 + row) * N2v + n0 + col4 * 4;
                CP16(s, gp);
            }
        }
        asm volatile("cp.async.commit_group;" ::: "memory");
    };

    float acc[2][8][4];
    #pragma unroll
    for (int mt = 0; mt < 2; mt++)
        #pragma unroll
        for (int nt = 0; nt < 8; nt++)
            #pragma unroll
            for (int j = 0; j < 4; j++) acc[mt][nt][j] = 0.f;

    const int nc = K / KC;
    issue_stage(0);

    for (int c = 0; c < nc; c++) {
        if (c + 1 < nc) {
            issue_stage(c + 1);
            asm volatile("cp.async.wait_group 1;" ::: "memory");
        } else {
            asm volatile("cp.async.wait_group 0;" ::: "memory");
        }
        __syncthreads();

        const uint32_t* bb = smu + (c & 1) * BUFU32;
        #pragma unroll
        for (int ks = 0; ks < 2; ks++) {
            #pragma unroll
            for (int p = 0; p < 3; p++) {
                const int aoff = (p == 1) ? OF_ALO : OF_AHI;
                const int boff = (p == 2) ? OF_BLO : OF_BHI;
                uint32_t a[2][4];
                #pragma unroll
                for (int mt = 0; mt < 2; mt++) {
                    const uint32_t* pa = bb + aoff + (wm * 32 + mt * 16 + g) * PADW + ks * 8 + tig;
                    a[mt][0] = pa[0];
                    a[mt][1] = pa[8 * PADW];
                    a[mt][2] = pa[4];
                    a[mt][3] = pa[8 * PADW + 4];
                }
                const uint32_t* pb0 = bb + boff + (ks * 8 + tig) * SBW + wn * 64 + g;
                #pragma unroll
                for (int nt = 0; nt < 8; nt++) {
                    uint32_t b0 = pb0[nt * 8];
                    uint32_t b1 = pb0[nt * 8 + 4 * SBW];
                    mma_bf16(acc[0][nt], a[0], b0, b1);
                    mma_bf16(acc[1][nt], a[1], b0, b1);
                }
            }
        }
        __syncthreads();
    }

    // ---- epilogue: bias, store, fused BN stats ----
    #pragma unroll
    for (int mt = 0; mt < 2; mt++) {
        #pragma unroll
        for (int h = 0; h < 2; h++) {
            const int rloc = row0 + wm * 32 + mt * 16 + g + h * 8;
            const float bs = bias[rloc];
            float* p = C + ((size_t)bz * COv + rloc) * (size_t)N2v + n0 + wn * 64 + tig * 2;
            float s = 0.f, q = 0.f;
            #pragma unroll
            for (int nt = 0; nt < 8; nt++) {
                float v0 = acc[mt][nt][2 * h] + bs;
                float v1 = acc[mt][nt][2 * h + 1] + bs;
                s += v0 + v1;
                q = fmaf(v0, v0, fmaf(v1, v1, q));
                *(float2*)(p + nt * 8) = make_float2(v0, v1);
            }
            #pragma unroll
            for (int o = 1; o <= 2; o <<= 1) {
                s += __shfl_xor_sync(0xFFFFFFFFu, s, o);
                q += __shfl_xor_sync(0xFFFFFFFFu, q, o);
            }
            if (tig == 0) {
                atomicAdd(&gs[rloc], s);
                atomicAdd(&gq[rloc], q);
            }
        }
    }
}

// ---------------- 0) zero the stat accumulators ----------------
__global__ void zero_stats_kernel()
{
    const int t = threadIdx.x;
    g_s1[t] = 0.f; g_q1[t] = 0.f; g_s2[t] = 0.f; g_q2[t] = 0.f;
}

// ---------------- 1a) three_nn partials: 256 cands, 2 queries/thread ------------
__global__ void __launch_bounds__(256) knn3_part_kernel(
    const float* __restrict__ xyz2, const float* __restrict__ xyz1)
{
    __shared__ float4 sp[NCAND];                    // 4 KB
    const int b = blockIdx.y;
    const int z = blockIdx.z;
    const float* p1 = xyz1 + (size_t)b * 3 * N1v + z * NCAND;
    for (int j = threadIdx.x; j < NCAND; j += blockDim.x) {
        float x = p1[j], y = p1[N1v + j], zc = p1[2 * N1v + j];
        sp[j] = make_float4(x, y, zc, fmaf(x, x, fmaf(y, y, zc * zc)));
    }
    __syncthreads();

    const int nA = blockIdx.x * (256 * QPT) + threadIdx.x;
    const int nB = nA + 256;
    const float* p2 = xyz2 + (size_t)b * 3 * N2v;
    const float axA = -2.f * p2[nA], ayA = -2.f * p2[N2v + nA], azA = -2.f * p2[2 * N2v + nA];
    const float axB = -2.f * p2[nB], ayB = -2.f * p2[N2v + nB], azB = -2.f * p2[2 * N2v + nB];

    float a0 = 3.4e38f, a1 = 3.4e38f, a2 = 3.4e38f;
    float b0 = 3.4e38f, b1 = 3.4e38f, b2 = 3.4e38f;
    int ai0 = 0, ai1 = 0, ai2 = 0, bi0 = 0, bi1 = 0, bi2 = 0;
    #pragma unroll 8
    for (int j = 0; j < NCAND; j++) {
        float4 q = sp[j];
        float dA = fmaf(q.x, axA, fmaf(q.y, ayA, fmaf(q.z, azA, q.w)));
        float dB = fmaf(q.x, axB, fmaf(q.y, ayB, fmaf(q.z, azB, q.w)));
        if (dA < a2) {
            if (dA < a1) {
                a2 = a1; ai2 = ai1;
                if (dA < a0) { a1 = a0; ai1 = ai0; a0 = dA; ai0 = j; }
                else         { a1 = dA; ai1 = j; }
            } else { a2 = dA; ai2 = j; }
        }
        if (dB < b2) {
            if (dB < b1) {
                b2 = b1; bi2 = bi1;
                if (dB < b0) { b1 = b0; bi1 = bi0; b0 = dB; bi0 = j; }
                else         { b1 = dB; bi1 = j; }
            } else { b2 = dB; bi2 = j; }
        }
    }
    const int jb = z * NCAND;
    const size_t baseA = ((size_t)(b * NSPLIT + z) * 3) * N2v + nA;
    g_pk[baseA] = a0;            g_pi[baseA] = jb + ai0;
    g_pk[baseA + N2v] = a1;      g_pi[baseA + N2v] = jb + ai1;
    g_pk[baseA + 2 * N2v] = a2;  g_pi[baseA + 2 * N2v] = jb + ai2;
    const size_t baseB = baseA + 256;
    g_pk[baseB] = b0;            g_pi[baseB] = jb + bi0;
    g_pk[baseB + N2v] = b1;      g_pi[baseB + N2v] = jb + bi1;
    g_pk[baseB + 2 * N2v] = b2;  g_pi[baseB + 2 * N2v] = jb + bi2;
}

// ---------------- 1b) merge 24 partials -> top-3, exact dists, weights ----------
__global__ void __launch_bounds__(256) knn3_merge_kernel(
    const float* __restrict__ xyz2, const float* __restrict__ xyz1)
{
    const int gid = blockIdx.x * blockDim.x + threadIdx.x;
    const int b = gid >> 13, n = gid & (N2v - 1);

    float d0 = 3.4e38f, d1 = 3.4e38f, d2 = 3.4e38f;
    int i0 = 0, i1 = 0, i2 = 0;
    #pragma unroll
    for (int z = 0; z < NSPLIT; z++) {
        #pragma unroll
        for (int r = 0; r < 3; r++) {
            const size_t o = ((size_t)(b * NSPLIT + z) * 3 + r) * N2v + n;
            float d = g_pk[o];
            int ii = g_pi[o];
            if (d < d2) {
                if (d < d1) {
                    d2 = d1; i2 = i1;
                    if (d < d0) { d1 = d0; i1 = i0; d0 = d; i0 = ii; }
                    else        { d1 = d;  i1 = ii; }
                } else { d2 = d; i2 = ii; }
            }
        }
    }

    const float* p2 = xyz2 + (size_t)b * 3 * N2v;
    const float px = p2[n], py = p2[N2v + n], pz = p2[2 * N2v + n];
    const float* p1 = xyz1 + (size_t)b * 3 * N1v;
    auto exact = [&](int i) {
        float dx = px - p1[i], dy = py - p1[N1v + i], dz = pz - p1[2 * N1v + i];
        return fmaf(dx, dx, fmaf(dy, dy, dz * dz));
    };
    float e0 = fmaxf(exact(i0), 1e-10f);
    float e1 = fmaxf(exact(i1), 1e-10f);
    float e2 = fmaxf(exact(i2), 1e-10f);
    float w0 = 1.f / e0, w1 = 1.f / e1, w2 = 1.f / e2;
    float s = 1.f / (w0 + w1 + w2);
    const int base = b * 3 * N2v + n;
    g_idx[base] = i0; g_idx[base + N2v] = i1; g_idx[base + 2 * N2v] = i2;
    g_wgt[base] = w0 * s; g_wgt[base + N2v] = w1 * s; g_wgt[base + 2 * N2v] = w2 * s;
}

// ---------------- 2) gather + interpolation -> pair-packed B1 planes ------------
#define CPB 4
__global__ void __launch_bounds__(256) interp_kernel(const float* __restrict__ feat1)
{
    __shared__ float sf[CPB][N1v];
    const int b = blockIdx.y;
    const int c0 = blockIdx.x * CPB;
    const float* f = feat1 + ((size_t)b * C1v + c0) * N1v;
    for (int t = threadIdx.x; t < CPB * N1v; t += blockDim.x)
        (&sf[0][0])[t] = f[t];
    __syncthreads();

    const int base = b * 3 * N2v;
    const size_t o0 = ((size_t)b * (K1v / 2) + c0 / 2) * N2v;
    for (int n = threadIdx.x; n < N2v; n += blockDim.x) {
        const int i0 = g_idx[base + n];
        const int i1 = g_idx[base + N2v + n];
        const int i2 = g_idx[base + 2 * N2v + n];
        const float w0 = g_wgt[base + n];
        const float w1 = g_wgt[base + N2v + n];
        const float w2 = g_wgt[base + 2 * N2v + n];
        float v[CPB];
        #pragma unroll
        for (int c = 0; c < CPB; c++)
            v[c] = sf[c][i0] * w0 + sf[c][i1] * w1 + sf[c][i2] * w2;
        uint32_t l01, l23;
        uint32_t h01 = pack_hi_lo(v[0], v[1], l01);
        uint32_t h23 = pack_hi_lo(v[2], v[3], l23);
        g_bh1[o0 + n] = h01;        g_bl1[o0 + n] = l01;
        g_bh1[o0 + N2v + n] = h23;  g_bl1[o0 + N2v + n] = l23;
    }
}

// ---------------- 2b) feat2 -> pair-packed B1 planes ----------------------------
__global__ void __launch_bounds__(256) f2cvt_kernel(const float* __restrict__ f2)
{
    const size_t gid = (size_t)blockIdx.x * 256 + threadIdx.x;
    const int n4 = (int)(gid & 2047);
    const int i = (int)((gid >> 11) & 63);
    const int b = (int)(gid >> 17);
    const float* r0 = f2 + ((size_t)b * C2v + 2 * i) * N2v + n4 * 4;
    float4 a = *(const float4*)r0;
    float4 c = *(const float4*)(r0 + N2v);
    uint32_t h[4], l[4];
    h[0] = pack_hi_lo(a.x, c.x, l[0]);
    h[1] = pack_hi_lo(a.y, c.y, l[1]);
    h[2] = pack_hi_lo(a.z, c.z, l[2]);
    h[3] = pack_hi_lo(a.w, c.w, l[3]);
    const size_t o = ((size_t)b * (K1v / 2) + 128 + i) * N2v + n4 * 4;
    *(uint4*)(g_bh1 + o) = make_uint4(h[0], h[1], h[2], h[3]);
    *(uint4*)(g_bl1 + o) = make_uint4(l[0], l[1], l[2], l[3]);
}

// ---------------- weight split ----------------
__global__ void wcvt_kernel(const float* __restrict__ src,
                            __nv_bfloat16* __restrict__ dh, __nv_bfloat16* __restrict__ dl)
{
    const size_t i4 = (size_t)blockIdx.x * 256 + threadIdx.x;
    float4 v = ((const float4*)src)[i4];
    uint32_t l01, l23;
    uint32_t h01 = pack_hi_lo(v.x, v.y, l01);
    uint32_t h23 = pack_hi_lo(v.z, v.w, l23);
    *(uint2*)(dh + i4 * 4) = make_uint2(h01, h23);
    *(uint2*)(dl + i4 * 4) = make_uint2(l01, l23);
}

// ---------------- BN1+ReLU on fp32 y1 -> pair-packed B2 planes ----------------
__global__ void __launch_bounds__(256) bnsplit_kernel(
    const float* __restrict__ y1, const float* __restrict__ sc, const float* __restrict__ sh)
{
    const size_t gid = (size_t)blockIdx.x * 256 + threadIdx.x;
    const int n4 = (int)(gid & 2047);
    const int i = (int)((gid >> 11) & 127);
    const int b = (int)(gid >> 18);
    const int c0 = 2 * i, c1 = 2 * i + 1;
    const float* r0 = y1 + ((size_t)b * COv + c0) * N2v + n4 * 4;
    float4 a = *(const float4*)r0;
    float4 c = *(const float4*)(r0 + N2v);
    const float s0 = sc[c0], t0 = sh[c0], s1 = sc[c1], t1 = sh[c1];
    a.x = fmaxf(fmaf(a.x, s0, t0), 0.f); a.y = fmaxf(fmaf(a.y, s0, t0), 0.f);
    a.z = fmaxf(fmaf(a.z, s0, t0), 0.f); a.w = fmaxf(fmaf(a.w, s0, t0), 0.f);
    c.x = fmaxf(fmaf(c.x, s1, t1), 0.f); c.y = fmaxf(fmaf(c.y, s1, t1), 0.f);
    c.z = fmaxf(fmaf(c.z, s1, t1), 0.f); c.w = fmaxf(fmaf(c.w, s1, t1), 0.f);
    uint32_t h[4], l[4];
    h[0] = pack_hi_lo(a.x, c.x, l[0]);
    h[1] = pack_hi_lo(a.y, c.y, l[1]);
    h[2] = pack_hi_lo(a.z, c.z, l[2]);
    h[3] = pack_hi_lo(a.w, c.w, l[3]);
    const size_t o = ((size_t)b * (COv / 2) + i) * N2v + n4 * 4;
    *(uint4*)(g_bh2 + o) = make_uint4(h[0], h[1], h[2], h[3]);
    *(uint4*)(g_bl2 + o) = make_uint4(l[0], l[1], l[2], l[3]);
}

// ---------------- stats -> folded scale/shift ----------------
__global__ void bnfinalize_kernel(
    const float* __restrict__ gs, const float* __restrict__ gq,
    const float* __restrict__ gamma, const float* __restrict__ beta,
    float* __restrict__ sc, float* __restrict__ sh)
{
    const int c = threadIdx.x;
    const double cnt = (double)BATCH * (double)N2v;
    double mean = (double)gs[c] / cnt;
    double var = (double)gq[c] / cnt - mean * mean;
    float inv = (float)(1.0 / sqrt(var + 1e-3));
    float scale = gamma[c] * inv;
    sc[c] = scale;
    sh[c] = beta[c] - (float)mean * scale;
}

// ---------------- final BN+ReLU in place on d_out ----------------
__global__ void __launch_bounds__(256) bnapply_kernel(
    float* __restrict__ Y, const float* __restrict__ sc, const float* __restrict__ sh)
{
    const size_t i = ((size_t)blockIdx.x * blockDim.x + threadIdx.x) * 4;
    const int c = (int)((i >> 13) & (COv - 1));
    float4 v = *(float4*)(Y + i);
    const float s = sc[c], t = sh[c];
    v.x = fmaxf(fmaf(v.x, s, t), 0.f);
    v.y = fmaxf(fmaf(v.y, s, t), 0.f);
    v.z = fmaxf(fmaf(v.z, s, t), 0.f);
    v.w = fmaxf(fmaf(v.w, s, t), 0.f);
    *(float4*)(Y + i) = v;
}

// ---------------- launch ----------------
extern "C" void kernel_launch(void* const* d_in, const int* in_sizes, int n_in,
                              void* d_out, int out_size)
{
    const float* xyz2  = (const float*)d_in[0];
    const float* xyz1  = (const float*)d_in[1];
    const float* feat2 = (const float*)d_in[2];
    const float* feat1 = (const float*)d_in[3];
    const float* W1    = (const float*)d_in[4];
    const float* b1    = (const float*)d_in[5];
    const float* g1    = (const float*)d_in[6];
    const float* be1   = (const float*)d_in[7];
    const float* W2    = (const float*)d_in[8];
    const float* b2    = (const float*)d_in[9];
    const float* g2    = (const float*)d_in[10];
    const float* be2   = (const float*)d_in[11];
    float* out = (float*)d_out;

    float *y1, *sc1, *sh1, *sc2, *sh2, *s1, *q1, *s2, *q2;
    __nv_bfloat16 *ah1, *al1, *ah2, *al2;
    uint32_t *bh1, *bl1, *bh2, *bl2;
    cudaGetSymbolAddress((void**)&y1,  g_y1);
    cudaGetSymbolAddress((void**)&sc1, g_sc1);
    cudaGetSymbolAddress((void**)&sh1, g_sh1);
    cudaGetSymbolAddress((void**)&sc2, g_sc2);
    cudaGetSymbolAddress((void**)&sh2, g_sh2);
    cudaGetSymbolAddress((void**)&s1,  g_s1);
    cudaGetSymbolAddress((void**)&q1,  g_q1);
    cudaGetSymbolAddress((void**)&s2,  g_s2);
    cudaGetSymbolAddress((void**)&q2,  g_q2);
    cudaGetSymbolAddress((void**)&ah1, g_ah1);
    cudaGetSymbolAddress((void**)&al1, g_al1);
    cudaGetSymbolAddress((void**)&ah2, g_ah2);
    cudaGetSymbolAddress((void**)&al2, g_al2);
    cudaGetSymbolAddress((void**)&bh1, g_bh1);
    cudaGetSymbolAddress((void**)&bl1, g_bl1);
    cudaGetSymbolAddress((void**)&bh2, g_bh2);
    cudaGetSymbolAddress((void**)&bl2, g_bl2);

    cudaFuncSetAttribute(tgemm_kernel, cudaFuncAttributeMaxDynamicSharedMemorySize, SM_BYTES);

    zero_stats_kernel<<<1, COv>>>();
    wcvt_kernel<<<(COv * K1v) / 1024, 256>>>(W1, ah1, al1);
    wcvt_kernel<<<(COv * COv) / 1024, 256>>>(W2, ah2, al2);
    knn3_part_kernel<<<dim3(N2v / (256 * QPT), BATCH, NSPLIT), 256>>>(xyz2, xyz1);
    knn3_merge_kernel<<<(BATCH * N2v) / 256, 256>>>(xyz2, xyz1);
    interp_kernel<<<dim3(C1v / CPB, BATCH), 256>>>(feat1);
    f2cvt_kernel<<<((size_t)BATCH * (C2v / 2) * (N2v / 4)) / 256, 256>>>(feat2);
    tgemm_kernel<<<dim3(N2v / BN, COv / BM, BATCH), 256, SM_BYTES>>>(
        ah1, al1, bh1, bl1, y1, K1v, b1, s1, q1);
    bnfinalize_kernel<<<1, COv>>>(s1, q1, g1, be1, sc1, sh1);
    bnsplit_kernel<<<((size_t)BATCH * (COv / 2) * (N2v / 4)) / 256, 256>>>(y1, sc1, sh1);
    tgemm_kernel<<<dim3(N2v / BN, COv / BM, BATCH), 256, SM_BYTES>>>(
        ah2, al2, bh2, bl2, out, COv, b2, s2, q2);
    bnfinalize_kernel<<<1, COv>>>(s2, q2, g2, be2, sc2, sh2);
    bnapply_kernel<<<((size_t)BATCH * COv * N2v) / 1024, 256>>>(out, sc2, sh2);
}

// round 16
// speedup vs baseline: 1.0283x; 1.0222x over previous
#include <cuda_runtime.h>
#include <cuda_bf16.h>
#include <cstdint>
#include <math.h>

#define BATCH 8
#define N2v 8192
#define N1v 2048
#define C1v 256
#define C2v 128
#define K1v 384
#define COv 256

#define NSPLIT 4
#define NCAND (N1v / NSPLIT)

#define BM 128
#define BN 128
#define KC 32
#define PADW 20                    // A row stride in u32
#define SBW 136                    // B row stride in u32
#define OF_AHI 0
#define OF_ALO 2560                // 128*20
#define OF_BHI 5120
#define OF_BLO (5120 + 16 * SBW)   // 7296
#define BUFU32 (OF_BLO + 16 * SBW) // 9472
#define SM_BYTES (2 * BUFU32 * 4)  // 75776

// ---------------- scratch (static device globals; no allocation) ----------------
__device__ float g_y1[(size_t)BATCH * COv * N2v];
__device__ int   g_idx[BATCH * 3 * N2v];
__device__ float g_wgt[BATCH * 3 * N2v];
__device__ float g_pk[BATCH * NSPLIT * 3 * N2v];
__device__ int   g_pi[BATCH * NSPLIT * 3 * N2v];
__device__ float g_sc1[COv], g_sh1[COv], g_sc2[COv], g_sh2[COv];
__device__ float g_s1[COv], g_q1[COv], g_s2[COv], g_q2[COv];
__device__ __align__(16) __nv_bfloat16 g_ah1[COv * K1v], g_al1[COv * K1v];
__device__ __align__(16) __nv_bfloat16 g_ah2[COv * COv], g_al2[COv * COv];
__device__ uint32_t g_bh1[(size_t)BATCH * (K1v / 2) * N2v], g_bl1[(size_t)BATCH * (K1v / 2) * N2v];
__device__ uint32_t g_bh2[(size_t)BATCH * (COv / 2) * N2v], g_bl2[(size_t)BATCH * (COv / 2) * N2v];

__device__ __forceinline__ uint32_t s2u(const void* p) {
    uint32_t a;
    asm("{ .reg .u64 t; cvta.to.shared.u64 t, %1; cvt.u32.u64 %0, t; }" : "=r"(a) : "l"(p));
    return a;
}
__device__ __forceinline__ uint32_t pack_hi_lo(float v0, float v1, uint32_t& lop) {
    __nv_bfloat16 h0 = __float2bfloat16_rn(v0);
    __nv_bfloat16 h1 = __float2bfloat16_rn(v1);
    __nv_bfloat16 l0 = __float2bfloat16_rn(v0 - __bfloat162float(h0));
    __nv_bfloat16 l1 = __float2bfloat16_rn(v1 - __bfloat162float(h1));
    lop = (uint32_t)__bfloat16_as_ushort(l0) | ((uint32_t)__bfloat16_as_ushort(l1) << 16);
    return (uint32_t)__bfloat16_as_ushort(h0) | ((uint32_t)__bfloat16_as_ushort(h1) << 16);
}
__device__ __forceinline__ void mma_bf16(float* c, const uint32_t* a, uint32_t b0, uint32_t b1) {
    asm volatile(
        "mma.sync.aligned.m16n8k16.row.col.f32.bf16.bf16.f32 "
        "{%0,%1,%2,%3}, {%4,%5,%6,%7}, {%8,%9}, {%0,%1,%2,%3};"
        : "+f"(c[0]), "+f"(c[1]), "+f"(c[2]), "+f"(c[3])
        : "r"(a[0]), "r"(a[1]), "r"(a[2]), "r"(a[3]), "r"(b0), "r"(b1));
}
#define CP16(s, g) asm volatile("cp.async.cg.shared.global [%0], [%1], 16;" :: "r"(s), "l"(g))

// ---------------- bf16 3-product HMMA GEMM, 2-stage cp.async, 2 CTA/SM ----------
// Hot loop restructured for operand reuse: Ah/Al/Bh loaded once per ks,
// products ordered p0(Ah*Bh), p1(Al*Bh), p2(Ah*Bl) per acc (same FP order).
__global__ void __launch_bounds__(256, 2) tgemm_kernel(
    const __nv_bfloat16* __restrict__ Ah, const __nv_bfloat16* __restrict__ Al,
    const uint32_t* __restrict__ Bhp, const uint32_t* __restrict__ Blp,
    float* __restrict__ C, int K,
    const float* __restrict__ bias,
    float* __restrict__ gs, float* __restrict__ gq)
{
    extern __shared__ uint32_t smu[];
    const uint32_t sb = s2u(smu);
    const int tid = threadIdx.x;
    const int lane = tid & 31, wid = tid >> 5;
    const int wm = wid & 3, wn = wid >> 2;
    const int g = lane >> 2, tig = lane & 3;
    const int row0 = blockIdx.y * BM;
    const int n0 = blockIdx.x * BN;
    const int bz = blockIdx.z;

    const uint32_t* Bh = Bhp + (size_t)bz * (K / 2) * N2v;
    const uint32_t* Bl = Blp + (size_t)bz * (K / 2) * N2v;

    auto issue_stage = [&](int c) {
        const int buf = c & 1;
        const uint32_t base = sb + buf * (BUFU32 * 4);
        #pragma unroll
        for (int p = 0; p < 2; p++) {
            const __nv_bfloat16* Ag = p ? Al : Ah;
            #pragma unroll
            for (int i = 0; i < 2; i++) {
                int seg = tid + i * 256;
                int row = seg >> 2, off = seg & 3;
                uint32_t s = base + (p ? OF_ALO * 4 : 0) + row * (PADW * 4) + off * 16;
                const void* gp = Ag + (size_t)(row0 + row) * K + c * KC + off * 8;
                CP16(s, gp);
            }
        }
        #pragma unroll
        for (int p = 0; p < 2; p++) {
            const uint32_t* Bg = p ? Bl : Bh;
            #pragma unroll
            for (int i = 0; i < 2; i++) {
                int seg = tid + i * 256;
                int row = seg >> 5, col4 = seg & 31;
                uint32_t s = base + (p ? OF_BLO * 4 : OF_BHI * 4) + (row * SBW + col4 * 4) * 4;
                const void* gp = Bg + (size_t)(c * 16 + row) * N2v + n0 + col4 * 4;
                CP16(s, gp);
            }
        }
        asm volatile("cp.async.commit_group;" ::: "memory");
    };

    float acc[2][8][4];
    #pragma unroll
    for (int mt = 0; mt < 2; mt++)
        #pragma unroll
        for (int nt = 0; nt < 8; nt++)
            #pragma unroll
            for (int j = 0; j < 4; j++) acc[mt][nt][j] = 0.f;

    const int nc = K / KC;
    issue_stage(0);

    for (int c = 0; c < nc; c++) {
        if (c + 1 < nc) {
            issue_stage(c + 1);
            asm volatile("cp.async.wait_group 1;" ::: "memory");
        } else {
            asm volatile("cp.async.wait_group 0;" ::: "memory");
        }
        __syncthreads();

        const uint32_t* bb = smu + (c & 1) * BUFU32;
        #pragma unroll
        for (int ks = 0; ks < 2; ks++) {
            // A fragments (both planes) — loaded once
            uint32_t ah[2][4], al[2][4];
            #pragma unroll
            for (int mt = 0; mt < 2; mt++) {
                const uint32_t* ph = bb + OF_AHI + (wm * 32 + mt * 16 + g) * PADW + ks * 8 + tig;
                ah[mt][0] = ph[0];
                ah[mt][1] = ph[8 * PADW];
                ah[mt][2] = ph[4];
                ah[mt][3] = ph[8 * PADW + 4];
                const uint32_t* pl = ph + (OF_ALO - OF_AHI);
                al[mt][0] = pl[0];
                al[mt][1] = pl[8 * PADW];
                al[mt][2] = pl[4];
                al[mt][3] = pl[8 * PADW + 4];
            }
            // B hi fragments — loaded once, used by p0 and p1
            const uint32_t* pbh = bb + OF_BHI + (ks * 8 + tig) * SBW + wn * 64 + g;
            uint32_t bh[8][2];
            #pragma unroll
            for (int nt = 0; nt < 8; nt++) {
                bh[nt][0] = pbh[nt * 8];
                bh[nt][1] = pbh[nt * 8 + 4 * SBW];
            }
            // p0: Ah * Bh
            #pragma unroll
            for (int nt = 0; nt < 8; nt++) {
                mma_bf16(acc[0][nt], ah[0], bh[nt][0], bh[nt][1]);
                mma_bf16(acc[1][nt], ah[1], bh[nt][0], bh[nt][1]);
            }
            // p1: Al * Bh
            #pragma unroll
            for (int nt = 0; nt < 8; nt++) {
                mma_bf16(acc[0][nt], al[0], bh[nt][0], bh[nt][1]);
                mma_bf16(acc[1][nt], al[1], bh[nt][0], bh[nt][1]);
            }
            // B lo fragments — loaded once, used by p2
            const uint32_t* pbl = bb + OF_BLO + (ks * 8 + tig) * SBW + wn * 64 + g;
            uint32_t bl[8][2];
            #pragma unroll
            for (int nt = 0; nt < 8; nt++) {
                bl[nt][0] = pbl[nt * 8];
                bl[nt][1] = pbl[nt * 8 + 4 * SBW];
            }
            // p2: Ah * Bl
            #pragma unroll
            for (int nt = 0; nt < 8; nt++) {
                mma_bf16(acc[0][nt], ah[0], bl[nt][0], bl[nt][1]);
                mma_bf16(acc[1][nt], ah[1], bl[nt][0], bl[nt][1]);
            }
        }
        __syncthreads();
    }

    // ---- epilogue: bias, store, fused BN stats ----
    #pragma unroll
    for (int mt = 0; mt < 2; mt++) {
        #pragma unroll
        for (int h = 0; h < 2; h++) {
            const int rloc = row0 + wm * 32 + mt * 16 + g + h * 8;
            const float bs = bias[rloc];
            float* p = C + ((size_t)bz * COv + rloc) * (size_t)N2v + n0 + wn * 64 + tig * 2;
            float s = 0.f, q = 0.f;
            #pragma unroll
            for (int nt = 0; nt < 8; nt++) {
                float v0 = acc[mt][nt][2 * h] + bs;
                float v1 = acc[mt][nt][2 * h + 1] + bs;
                s += v0 + v1;
                q = fmaf(v0, v0, fmaf(v1, v1, q));
                *(float2*)(p + nt * 8) = make_float2(v0, v1);
            }
            #pragma unroll
            for (int o = 1; o <= 2; o <<= 1) {
                s += __shfl_xor_sync(0xFFFFFFFFu, s, o);
                q += __shfl_xor_sync(0xFFFFFFFFu, q, o);
            }
            if (tig == 0) {
                atomicAdd(&gs[rloc], s);
                atomicAdd(&gq[rloc], q);
            }
        }
    }
}

// ---------------- 0) zero the stat accumulators ----------------
__global__ void zero_stats_kernel()
{
    const int t = threadIdx.x;
    g_s1[t] = 0.f; g_q1[t] = 0.f; g_s2[t] = 0.f; g_q2[t] = 0.f;
}

// ---------------- 1a) three_nn partials (round-9 verified, QPT=1) ---------------
__global__ void __launch_bounds__(256) knn3_part_kernel(
    const float* __restrict__ xyz2, const float* __restrict__ xyz1)
{
    __shared__ float4 sp[NCAND];
    const int b = blockIdx.y;
    const int z = blockIdx.z;
    const float* p1 = xyz1 + (size_t)b * 3 * N1v + z * NCAND;
    for (int j = threadIdx.x; j < NCAND; j += blockDim.x) {
        float x = p1[j], y = p1[N1v + j], zc = p1[2 * N1v + j];
        sp[j] = make_float4(x, y, zc, fmaf(x, x, fmaf(y, y, zc * zc)));
    }
    __syncthreads();

    const int n = blockIdx.x * blockDim.x + threadIdx.x;
    const float* p2 = xyz2 + (size_t)b * 3 * N2v;
    const float px = p2[n], py = p2[N2v + n], pz = p2[2 * N2v + n];
    const float ax = -2.f * px, ay = -2.f * py, az = -2.f * pz;

    float d0 = 3.4e38f, d1 = 3.4e38f, d2 = 3.4e38f;
    int i0 = 0, i1 = 0, i2 = 0;
    #pragma unroll 8
    for (int j = 0; j < NCAND; j++) {
        float4 q = sp[j];
        float d = fmaf(q.x, ax, fmaf(q.y, ay, fmaf(q.z, az, q.w)));
        if (d < d2) {
            if (d < d1) {
                d2 = d1; i2 = i1;
                if (d < d0) { d1 = d0; i1 = i0; d0 = d; i0 = j; }
                else        { d1 = d;  i1 = j; }
            } else { d2 = d; i2 = j; }
        }
    }
    const int jb = z * NCAND;
    const size_t base = ((size_t)(b * NSPLIT + z) * 3) * N2v + n;
    g_pk[base] = d0;            g_pi[base] = jb + i0;
    g_pk[base + N2v] = d1;      g_pi[base + N2v] = jb + i1;
    g_pk[base + 2 * N2v] = d2;  g_pi[base + 2 * N2v] = jb + i2;
}

// ---------------- 1b) merge partials -> top-3, exact dists, weights -------------
__global__ void __launch_bounds__(256) knn3_merge_kernel(
    const float* __restrict__ xyz2, const float* __restrict__ xyz1)
{
    const int gid = blockIdx.x * blockDim.x + threadIdx.x;
    const int b = gid >> 13, n = gid & (N2v - 1);

    float d0 = 3.4e38f, d1 = 3.4e38f, d2 = 3.4e38f;
    int i0 = 0, i1 = 0, i2 = 0;
    #pragma unroll
    for (int z = 0; z < NSPLIT; z++) {
        #pragma unroll
        for (int r = 0; r < 3; r++) {
            const size_t o = ((size_t)(b * NSPLIT + z) * 3 + r) * N2v + n;
            float d = g_pk[o];
            int ii = g_pi[o];
            if (d < d2) {
                if (d < d1) {
                    d2 = d1; i2 = i1;
                    if (d < d0) { d1 = d0; i1 = i0; d0 = d; i0 = ii; }
                    else        { d1 = d;  i1 = ii; }
                } else { d2 = d; i2 = ii; }
            }
        }
    }

    const float* p2 = xyz2 + (size_t)b * 3 * N2v;
    const float px = p2[n], py = p2[N2v + n], pz = p2[2 * N2v + n];
    const float* p1 = xyz1 + (size_t)b * 3 * N1v;
    auto exact = [&](int i) {
        float dx = px - p1[i], dy = py - p1[N1v + i], dz = pz - p1[2 * N1v + i];
        return fmaf(dx, dx, fmaf(dy, dy, dz * dz));
    };
    float e0 = fmaxf(exact(i0), 1e-10f);
    float e1 = fmaxf(exact(i1), 1e-10f);
    float e2 = fmaxf(exact(i2), 1e-10f);
    float w0 = 1.f / e0, w1 = 1.f / e1, w2 = 1.f / e2;
    float s = 1.f / (w0 + w1 + w2);
    const int base = b * 3 * N2v + n;
    g_idx[base] = i0; g_idx[base + N2v] = i1; g_idx[base + 2 * N2v] = i2;
    g_wgt[base] = w0 * s; g_wgt[base + N2v] = w1 * s; g_wgt[base + 2 * N2v] = w2 * s;
}

// ---------------- 2) gather + interpolation -> pair-packed B1 planes ------------
#define CPB 4
__global__ void __launch_bounds__(256) interp_kernel(const float* __restrict__ feat1)
{
    __shared__ float sf[CPB][N1v];
    const int b = blockIdx.y;
    const int c0 = blockIdx.x * CPB;
    const float* f = feat1 + ((size_t)b * C1v + c0) * N1v;
    for (int t = threadIdx.x; t < CPB * N1v; t += blockDim.x)
        (&sf[0][0])[t] = f[t];
    __syncthreads();

    const int base = b * 3 * N2v;
    const size_t o0 = ((size_t)b * (K1v / 2) + c0 / 2) * N2v;
    for (int n = threadIdx.x; n < N2v; n += blockDim.x) {
        const int i0 = g_idx[base + n];
        const int i1 = g_idx[base + N2v + n];
        const int i2 = g_idx[base + 2 * N2v + n];
        const float w0 = g_wgt[base + n];
        const float w1 = g_wgt[base + N2v + n];
        const float w2 = g_wgt[base + 2 * N2v + n];
        float v[CPB];
        #pragma unroll
        for (int c = 0; c < CPB; c++)
            v[c] = sf[c][i0] * w0 + sf[c][i1] * w1 + sf[c][i2] * w2;
        uint32_t l01, l23;
        uint32_t h01 = pack_hi_lo(v[0], v[1], l01);
        uint32_t h23 = pack_hi_lo(v[2], v[3], l23);
        g_bh1[o0 + n] = h01;        g_bl1[o0 + n] = l01;
        g_bh1[o0 + N2v + n] = h23;  g_bl1[o0 + N2v + n] = l23;
    }
}

// ---------------- 2b) feat2 -> pair-packed B1 planes ----------------------------
__global__ void __launch_bounds__(256) f2cvt_kernel(const float* __restrict__ f2)
{
    const size_t gid = (size_t)blockIdx.x * 256 + threadIdx.x;
    const int n4 = (int)(gid & 2047);
    const int i = (int)((gid >> 11) & 63);
    const int b = (int)(gid >> 17);
    const float* r0 = f2 + ((size_t)b * C2v + 2 * i) * N2v + n4 * 4;
    float4 a = *(const float4*)r0;
    float4 c = *(const float4*)(r0 + N2v);
    uint32_t h[4], l[4];
    h[0] = pack_hi_lo(a.x, c.x, l[0]);
    h[1] = pack_hi_lo(a.y, c.y, l[1]);
    h[2] = pack_hi_lo(a.z, c.z, l[2]);
    h[3] = pack_hi_lo(a.w, c.w, l[3]);
    const size_t o = ((size_t)b * (K1v / 2) + 128 + i) * N2v + n4 * 4;
    *(uint4*)(g_bh1 + o) = make_uint4(h[0], h[1], h[2], h[3]);
    *(uint4*)(g_bl1 + o) = make_uint4(l[0], l[1], l[2], l[3]);
}

// ---------------- weight split ----------------
__global__ void wcvt_kernel(const float* __restrict__ src,
                            __nv_bfloat16* __restrict__ dh, __nv_bfloat16* __restrict__ dl)
{
    const size_t i4 = (size_t)blockIdx.x * 256 + threadIdx.x;
    float4 v = ((const float4*)src)[i4];
    uint32_t l01, l23;
    uint32_t h01 = pack_hi_lo(v.x, v.y, l01);
    uint32_t h23 = pack_hi_lo(v.z, v.w, l23);
    *(uint2*)(dh + i4 * 4) = make_uint2(h01, h23);
    *(uint2*)(dl + i4 * 4) = make_uint2(l01, l23);
}

// ---------------- BN1+ReLU on fp32 y1 -> pair-packed B2 planes ----------------
__global__ void __launch_bounds__(256) bnsplit_kernel(
    const float* __restrict__ y1, const float* __restrict__ sc, const float* __restrict__ sh)
{
    const size_t gid = (size_t)blockIdx.x * 256 + threadIdx.x;
    const int n4 = (int)(gid & 2047);
    const int i = (int)((gid >> 11) & 127);
    const int b = (int)(gid >> 18);
    const int c0 = 2 * i, c1 = 2 * i + 1;
    const float* r0 = y1 + ((size_t)b * COv + c0) * N2v + n4 * 4;
    float4 a = *(const float4*)r0;
    float4 c = *(const float4*)(r0 + N2v);
    const float s0 = sc[c0], t0 = sh[c0], s1 = sc[c1], t1 = sh[c1];
    a.x = fmaxf(fmaf(a.x, s0, t0), 0.f); a.y = fmaxf(fmaf(a.y, s0, t0), 0.f);
    a.z = fmaxf(fmaf(a.z, s0, t0), 0.f); a.w = fmaxf(fmaf(a.w, s0, t0), 0.f);
    c.x = fmaxf(fmaf(c.x, s1, t1), 0.f); c.y = fmaxf(fmaf(c.y, s1, t1), 0.f);
    c.z = fmaxf(fmaf(c.z, s1, t1), 0.f); c.w = fmaxf(fmaf(c.w, s1, t1), 0.f);
    uint32_t h[4], l[4];
    h[0] = pack_hi_lo(a.x, c.x, l[0]);
    h[1] = pack_hi_lo(a.y, c.y, l[1]);
    h[2] = pack_hi_lo(a.z, c.z, l[2]);
    h[3] = pack_hi_lo(a.w, c.w, l[3]);
    const size_t o = ((size_t)b * (COv / 2) + i) * N2v + n4 * 4;
    *(uint4*)(g_bh2 + o) = make_uint4(h[0], h[1], h[2], h[3]);
    *(uint4*)(g_bl2 + o) = make_uint4(l[0], l[1], l[2], l[3]);
}

// ---------------- stats -> folded scale/shift ----------------
__global__ void bnfinalize_kernel(
    const float* __restrict__ gs, const float* __restrict__ gq,
    const float* __restrict__ gamma, const float* __restrict__ beta,
    float* __restrict__ sc, float* __restrict__ sh)
{
    const int c = threadIdx.x;
    const double cnt = (double)BATCH * (double)N2v;
    double mean = (double)gs[c] / cnt;
    double var = (double)gq[c] / cnt - mean * mean;
    float inv = (float)(1.0 / sqrt(var + 1e-3));
    float scale = gamma[c] * inv;
    sc[c] = scale;
    sh[c] = beta[c] - (float)mean * scale;
}

// ---------------- final BN+ReLU in place on d_out ----------------
__global__ void __launch_bounds__(256) bnapply_kernel(
    float* __restrict__ Y, const float* __restrict__ sc, const float* __restrict__ sh)
{
    const size_t i = ((size_t)blockIdx.x * blockDim.x + threadIdx.x) * 4;
    const int c = (int)((i >> 13) & (COv - 1));
    float4 v = *(float4*)(Y + i);
    const float s = sc[c], t = sh[c];
    v.x = fmaxf(fmaf(v.x, s, t), 0.f);
    v.y = fmaxf(fmaf(v.y, s, t), 0.f);
    v.z = fmaxf(fmaf(v.z, s, t), 0.f);
    v.w = fmaxf(fmaf(v.w, s, t), 0.f);
    *(float4*)(Y + i) = v;
}

// ---------------- launch ----------------
extern "C" void kernel_launch(void* const* d_in, const int* in_sizes, int n_in,
                              void* d_out, int out_size)
{
    const float* xyz2  = (const float*)d_in[0];
    const float* xyz1  = (const float*)d_in[1];
    const float* feat2 = (const float*)d_in[2];
    const float* feat1 = (const float*)d_in[3];
    const float* W1    = (const float*)d_in[4];
    const float* b1    = (const float*)d_in[5];
    const float* g1    = (const float*)d_in[6];
    const float* be1   = (const float*)d_in[7];
    const float* W2    = (const float*)d_in[8];
    const float* b2    = (const float*)d_in[9];
    const float* g2    = (const float*)d_in[10];
    const float* be2   = (const float*)d_in[11];
    float* out = (float*)d_out;

    float *y1, *sc1, *sh1, *sc2, *sh2, *s1, *q1, *s2, *q2;
    __nv_bfloat16 *ah1, *al1, *ah2, *al2;
    uint32_t *bh1, *bl1, *bh2, *bl2;
    cudaGetSymbolAddress((void**)&y1,  g_y1);
    cudaGetSymbolAddress((void**)&sc1, g_sc1);
    cudaGetSymbolAddress((void**)&sh1, g_sh1);
    cudaGetSymbolAddress((void**)&sc2, g_sc2);
    cudaGetSymbolAddress((void**)&sh2, g_sh2);
    cudaGetSymbolAddress((void**)&s1,  g_s1);
    cudaGetSymbolAddress((void**)&q1,  g_q1);
    cudaGetSymbolAddress((void**)&s2,  g_s2);
    cudaGetSymbolAddress((void**)&q2,  g_q2);
    cudaGetSymbolAddress((void**)&ah1, g_ah1);
    cudaGetSymbolAddress((void**)&al1, g_al1);
    cudaGetSymbolAddress((void**)&ah2, g_ah2);
    cudaGetSymbolAddress((void**)&al2, g_al2);
    cudaGetSymbolAddress((void**)&bh1, g_bh1);
    cudaGetSymbolAddress((void**)&bl1, g_bl1);
    cudaGetSymbolAddress((void**)&bh2, g_bh2);
    cudaGetSymbolAddress((void**)&bl2, g_bl2);

    cudaFuncSetAttribute(tgemm_kernel, cudaFuncAttributeMaxDynamicSharedMemorySize, SM_BYTES);

    zero_stats_kernel<<<1, COv>>>();
    wcvt_kernel<<<(COv * K1v) / 1024, 256>>>(W1, ah1, al1);
    wcvt_kernel<<<(COv * COv) / 1024, 256>>>(W2, ah2, al2);
    knn3_part_kernel<<<dim3(N2v / 256, BATCH, NSPLIT), 256>>>(xyz2, xyz1);
    knn3_merge_kernel<<<(BATCH * N2v) / 256, 256>>>(xyz2, xyz1);
    interp_kernel<<<dim3(C1v / CPB, BATCH), 256>>>(feat1);
    f2cvt_kernel<<<((size_t)BATCH * (C2v / 2) * (N2v / 4)) / 256, 256>>>(feat2);
    tgemm_kernel<<<dim3(N2v / BN, COv / BM, BATCH), 256, SM_BYTES>>>(
        ah1, al1, bh1, bl1, y1, K1v, b1, s1, q1);
    bnfinalize_kernel<<<1, COv>>>(s1, q1, g1, be1, sc1, sh1);
    bnsplit_kernel<<<((size_t)BATCH * (COv / 2) * (N2v / 4)) / 256, 256>>>(y1, sc1, sh1);
    tgemm_kernel<<<dim3(N2v / BN, COv / BM, BATCH), 256, SM_BYTES>>>(
        ah2, al2, bh2, bl2, out, COv, b2, s2, q2);
    bnfinalize_kernel<<<1, COv>>>(s2, q2, g2, be2, sc2, sh2);
    bnapply_kernel<<<((size_t)BATCH * COv * N2v) / 1024, 256>>>(out, sc2, sh2);
}

// round 17
// speedup vs baseline: 1.0338x; 1.0053x over previous
#include <cuda_runtime.h>
#include <cuda_bf16.h>
#include <cstdint>
#include <math.h>

#define BATCH 8
#define N2v 8192
#define N1v 2048
#define C1v 256
#define C2v 128
#define K1v 384
#define COv 256

#define NSPLIT 4
#define NCAND (N1v / NSPLIT)

#define BM 128
#define BN 128
#define KC 32
#define PADW 20                    // A row stride in u32
#define SBW 136                    // B row stride in u32
#define OF_AHI 0
#define OF_ALO 2560                // 128*20
#define OF_BHI 5120
#define OF_BLO (5120 + 16 * SBW)   // 7296
#define BUFU32 (OF_BLO + 16 * SBW) // 9472
#define SM_BYTES (2 * BUFU32 * 4)  // 75776

// ---------------- scratch (static device globals; no allocation) ----------------
__device__ float g_y1[(size_t)BATCH * COv * N2v];
__device__ int   g_idx[BATCH * 3 * N2v];
__device__ float g_wgt[BATCH * 3 * N2v];
__device__ float g_pk[BATCH * NSPLIT * 3 * N2v];
__device__ int   g_pi[BATCH * NSPLIT * 3 * N2v];
__device__ float g_s1[COv], g_q1[COv], g_s2[COv], g_q2[COv];
__device__ __align__(16) __nv_bfloat16 g_ah1[COv * K1v], g_al1[COv * K1v];
__device__ __align__(16) __nv_bfloat16 g_ah2[COv * COv], g_al2[COv * COv];
__device__ uint32_t g_bh1[(size_t)BATCH * (K1v / 2) * N2v], g_bl1[(size_t)BATCH * (K1v / 2) * N2v];
__device__ uint32_t g_bh2[(size_t)BATCH * (COv / 2) * N2v], g_bl2[(size_t)BATCH * (COv / 2) * N2v];

__device__ __forceinline__ uint32_t s2u(const void* p) {
    uint32_t a;
    asm("{ .reg .u64 t; cvta.to.shared.u64 t, %1; cvt.u32.u64 %0, t; }" : "=r"(a) : "l"(p));
    return a;
}
__device__ __forceinline__ uint32_t pack_hi_lo(float v0, float v1, uint32_t& lop) {
    __nv_bfloat16 h0 = __float2bfloat16_rn(v0);
    __nv_bfloat16 h1 = __float2bfloat16_rn(v1);
    __nv_bfloat16 l0 = __float2bfloat16_rn(v0 - __bfloat162float(h0));
    __nv_bfloat16 l1 = __float2bfloat16_rn(v1 - __bfloat162float(h1));
    lop = (uint32_t)__bfloat16_as_ushort(l0) | ((uint32_t)__bfloat16_as_ushort(l1) << 16);
    return (uint32_t)__bfloat16_as_ushort(h0) | ((uint32_t)__bfloat16_as_ushort(h1) << 16);
}
// folded BN scale/shift from raw sums (identical fp64 math to old bnfinalize)
__device__ __forceinline__ float2 bn_fold(float gs, float gq, float gamma, float beta) {
    const double cnt = (double)BATCH * (double)N2v;
    double mean = (double)gs / cnt;
    double var = (double)gq / cnt - mean * mean;
    float inv = (float)(1.0 / sqrt(var + 1e-3));
    float scale = gamma * inv;
    return make_float2(scale, beta - (float)mean * scale);
}
__device__ __forceinline__ void mma_bf16(float* c, const uint32_t* a, uint32_t b0, uint32_t b1) {
    asm volatile(
        "mma.sync.aligned.m16n8k16.row.col.f32.bf16.bf16.f32 "
        "{%0,%1,%2,%3}, {%4,%5,%6,%7}, {%8,%9}, {%0,%1,%2,%3};"
        : "+f"(c[0]), "+f"(c[1]), "+f"(c[2]), "+f"(c[3])
        : "r"(a[0]), "r"(a[1]), "r"(a[2]), "r"(a[3]), "r"(b0), "r"(b1));
}
#define CP16(s, g) asm volatile("cp.async.cg.shared.global [%0], [%1], 16;" :: "r"(s), "l"(g))

// ---------------- bf16 3-product HMMA GEMM, 2-stage cp.async, 2 CTA/SM ----------
__global__ void __launch_bounds__(256, 2) tgemm_kernel(
    const __nv_bfloat16* __restrict__ Ah, const __nv_bfloat16* __restrict__ Al,
    const uint32_t* __restrict__ Bhp, const uint32_t* __restrict__ Blp,
    float* __restrict__ C, int K,
    const float* __restrict__ bias,
    float* __restrict__ gs, float* __restrict__ gq)
{
    extern __shared__ uint32_t smu[];
    const uint32_t sb = s2u(smu);
    const int tid = threadIdx.x;
    const int lane = tid & 31, wid = tid >> 5;
    const int wm = wid & 3, wn = wid >> 2;
    const int g = lane >> 2, tig = lane & 3;
    const int row0 = blockIdx.y * BM;
    const int n0 = blockIdx.x * BN;
    const int bz = blockIdx.z;

    const uint32_t* Bh = Bhp + (size_t)bz * (K / 2) * N2v;
    const uint32_t* Bl = Blp + (size_t)bz * (K / 2) * N2v;

    auto issue_stage = [&](int c) {
        const int buf = c & 1;
        const uint32_t base = sb + buf * (BUFU32 * 4);
        #pragma unroll
        for (int p = 0; p < 2; p++) {
            const __nv_bfloat16* Ag = p ? Al : Ah;
            #pragma unroll
            for (int i = 0; i < 2; i++) {
                int seg = tid + i * 256;
                int row = seg >> 2, off = seg & 3;
                uint32_t s = base + (p ? OF_ALO * 4 : 0) + row * (PADW * 4) + off * 16;
                const void* gp = Ag + (size_t)(row0 + row) * K + c * KC + off * 8;
                CP16(s, gp);
            }
        }
        #pragma unroll
        for (int p = 0; p < 2; p++) {
            const uint32_t* Bg = p ? Bl : Bh;
            #pragma unroll
            for (int i = 0; i < 2; i++) {
                int seg = tid + i * 256;
                int row = seg >> 5, col4 = seg & 31;
                uint32_t s = base + (p ? OF_BLO * 4 : OF_BHI * 4) + (row * SBW + col4 * 4) * 4;
                const void* gp = Bg + (size_t)(c * 16 + row) * N2v + n0 + col4 * 4;
                CP16(s, gp);
            }
        }
        asm volatile("cp.async.commit_group;" ::: "memory");
    };

    float acc[2][8][4];
    #pragma unroll
    for (int mt = 0; mt < 2; mt++)
        #pragma unroll
        for (int nt = 0; nt < 8; nt++)
            #pragma unroll
            for (int j = 0; j < 4; j++) acc[mt][nt][j] = 0.f;

    const int nc = K / KC;
    issue_stage(0);

    for (int c = 0; c < nc; c++) {
        if (c + 1 < nc) {
            issue_stage(c + 1);
            asm volatile("cp.async.wait_group 1;" ::: "memory");
        } else {
            asm volatile("cp.async.wait_group 0;" ::: "memory");
        }
        __syncthreads();

        const uint32_t* bb = smu + (c & 1) * BUFU32;
        #pragma unroll
        for (int ks = 0; ks < 2; ks++) {
            uint32_t ah[2][4], al[2][4];
            #pragma unroll
            for (int mt = 0; mt < 2; mt++) {
                const uint32_t* ph = bb + OF_AHI + (wm * 32 + mt * 16 + g) * PADW + ks * 8 + tig;
                ah[mt][0] = ph[0];
                ah[mt][1] = ph[8 * PADW];
                ah[mt][2] = ph[4];
                ah[mt][3] = ph[8 * PADW + 4];
                const uint32_t* pl = ph + (OF_ALO - OF_AHI);
                al[mt][0] = pl[0];
                al[mt][1] = pl[8 * PADW];
                al[mt][2] = pl[4];
                al[mt][3] = pl[8 * PADW + 4];
            }
            const uint32_t* pbh = bb + OF_BHI + (ks * 8 + tig) * SBW + wn * 64 + g;
            uint32_t bh[8][2];
            #pragma unroll
            for (int nt = 0; nt < 8; nt++) {
                bh[nt][0] = pbh[nt * 8];
                bh[nt][1] = pbh[nt * 8 + 4 * SBW];
            }
            #pragma unroll
            for (int nt = 0; nt < 8; nt++) {
                mma_bf16(acc[0][nt], ah[0], bh[nt][0], bh[nt][1]);
                mma_bf16(acc[1][nt], ah[1], bh[nt][0], bh[nt][1]);
            }
            #pragma unroll
            for (int nt = 0; nt < 8; nt++) {
                mma_bf16(acc[0][nt], al[0], bh[nt][0], bh[nt][1]);
                mma_bf16(acc[1][nt], al[1], bh[nt][0], bh[nt][1]);
            }
            const uint32_t* pbl = bb + OF_BLO + (ks * 8 + tig) * SBW + wn * 64 + g;
            uint32_t bl[8][2];
            #pragma unroll
            for (int nt = 0; nt < 8; nt++) {
                bl[nt][0] = pbl[nt * 8];
                bl[nt][1] = pbl[nt * 8 + 4 * SBW];
            }
            #pragma unroll
            for (int nt = 0; nt < 8; nt++) {
                mma_bf16(acc[0][nt], ah[0], bl[nt][0], bl[nt][1]);
                mma_bf16(acc[1][nt], ah[1], bl[nt][0], bl[nt][1]);
            }
        }
        __syncthreads();
    }

    // ---- epilogue: bias, store, fused BN stats ----
    #pragma unroll
    for (int mt = 0; mt < 2; mt++) {
        #pragma unroll
        for (int h = 0; h < 2; h++) {
            const int rloc = row0 + wm * 32 + mt * 16 + g + h * 8;
            const float bs = bias[rloc];
            float* p = C + ((size_t)bz * COv + rloc) * (size_t)N2v + n0 + wn * 64 + tig * 2;
            float s = 0.f, q = 0.f;
            #pragma unroll
            for (int nt = 0; nt < 8; nt++) {
                float v0 = acc[mt][nt][2 * h] + bs;
                float v1 = acc[mt][nt][2 * h + 1] + bs;
                s += v0 + v1;
                q = fmaf(v0, v0, fmaf(v1, v1, q));
                *(float2*)(p + nt * 8) = make_float2(v0, v1);
            }
            #pragma unroll
            for (int o = 1; o <= 2; o <<= 1) {
                s += __shfl_xor_sync(0xFFFFFFFFu, s, o);
                q += __shfl_xor_sync(0xFFFFFFFFu, q, o);
            }
            if (tig == 0) {
                atomicAdd(&gs[rloc], s);
                atomicAdd(&gq[rloc], q);
            }
        }
    }
}

// ---------------- 1a) three_nn partials + stat-accumulator zeroing --------------
__global__ void __launch_bounds__(256) knn3_part_kernel(
    const float* __restrict__ xyz2, const float* __restrict__ xyz1)
{
    __shared__ float4 sp[NCAND];
    const int b = blockIdx.y;
    const int z = blockIdx.z;
    // block (0,0,0) zeroes the BN stat accumulators (used much later in-stream)
    if (blockIdx.x == 0 && b == 0 && z == 0) {
        const int t = threadIdx.x;
        g_s1[t] = 0.f; g_q1[t] = 0.f; g_s2[t] = 0.f; g_q2[t] = 0.f;
    }
    const float* p1 = xyz1 + (size_t)b * 3 * N1v + z * NCAND;
    for (int j = threadIdx.x; j < NCAND; j += blockDim.x) {
        float x = p1[j], y = p1[N1v + j], zc = p1[2 * N1v + j];
        sp[j] = make_float4(x, y, zc, fmaf(x, x, fmaf(y, y, zc * zc)));
    }
    __syncthreads();

    const int n = blockIdx.x * blockDim.x + threadIdx.x;
    const float* p2 = xyz2 + (size_t)b * 3 * N2v;
    const float px = p2[n], py = p2[N2v + n], pz = p2[2 * N2v + n];
    const float ax = -2.f * px, ay = -2.f * py, az = -2.f * pz;

    float d0 = 3.4e38f, d1 = 3.4e38f, d2 = 3.4e38f;
    int i0 = 0, i1 = 0, i2 = 0;
    #pragma unroll 8
    for (int j = 0; j < NCAND; j++) {
        float4 q = sp[j];
        float d = fmaf(q.x, ax, fmaf(q.y, ay, fmaf(q.z, az, q.w)));
        if (d < d2) {
            if (d < d1) {
                d2 = d1; i2 = i1;
                if (d < d0) { d1 = d0; i1 = i0; d0 = d; i0 = j; }
                else        { d1 = d;  i1 = j; }
            } else { d2 = d; i2 = j; }
        }
    }
    const int jb = z * NCAND;
    const size_t base = ((size_t)(b * NSPLIT + z) * 3) * N2v + n;
    g_pk[base] = d0;            g_pi[base] = jb + i0;
    g_pk[base + N2v] = d1;      g_pi[base + N2v] = jb + i1;
    g_pk[base + 2 * N2v] = d2;  g_pi[base + 2 * N2v] = jb + i2;
}

// ---------------- 1b) merge partials -> top-3, exact dists, weights -------------
__global__ void __launch_bounds__(256) knn3_merge_kernel(
    const float* __restrict__ xyz2, const float* __restrict__ xyz1)
{
    const int gid = blockIdx.x * blockDim.x + threadIdx.x;
    const int b = gid >> 13, n = gid & (N2v - 1);

    float d0 = 3.4e38f, d1 = 3.4e38f, d2 = 3.4e38f;
    int i0 = 0, i1 = 0, i2 = 0;
    #pragma unroll
    for (int z = 0; z < NSPLIT; z++) {
        #pragma unroll
        for (int r = 0; r < 3; r++) {
            const size_t o = ((size_t)(b * NSPLIT + z) * 3 + r) * N2v + n;
            float d = g_pk[o];
            int ii = g_pi[o];
            if (d < d2) {
                if (d < d1) {
                    d2 = d1; i2 = i1;
                    if (d < d0) { d1 = d0; i1 = i0; d0 = d; i0 = ii; }
                    else        { d1 = d;  i1 = ii; }
                } else { d2 = d; i2 = ii; }
            }
        }
    }

    const float* p2 = xyz2 + (size_t)b * 3 * N2v;
    const float px = p2[n], py = p2[N2v + n], pz = p2[2 * N2v + n];
    const float* p1 = xyz1 + (size_t)b * 3 * N1v;
    auto exact = [&](int i) {
        float dx = px - p1[i], dy = py - p1[N1v + i], dz = pz - p1[2 * N1v + i];
        return fmaf(dx, dx, fmaf(dy, dy, dz * dz));
    };
    float e0 = fmaxf(exact(i0), 1e-10f);
    float e1 = fmaxf(exact(i1), 1e-10f);
    float e2 = fmaxf(exact(i2), 1e-10f);
    float w0 = 1.f / e0, w1 = 1.f / e1, w2 = 1.f / e2;
    float s = 1.f / (w0 + w1 + w2);
    const int base = b * 3 * N2v + n;
    g_idx[base] = i0; g_idx[base + N2v] = i1; g_idx[base + 2 * N2v] = i2;
    g_wgt[base] = w0 * s; g_wgt[base + N2v] = w1 * s; g_wgt[base + 2 * N2v] = w2 * s;
}

// ---------------- 2) gather + interpolation -> pair-packed B1 planes ------------
#define CPB 4
__global__ void __launch_bounds__(256) interp_kernel(const float* __restrict__ feat1)
{
    __shared__ float sf[CPB][N1v];
    const int b = blockIdx.y;
    const int c0 = blockIdx.x * CPB;
    const float* f = feat1 + ((size_t)b * C1v + c0) * N1v;
    for (int t = threadIdx.x; t < CPB * N1v; t += blockDim.x)
        (&sf[0][0])[t] = f[t];
    __syncthreads();

    const int base = b * 3 * N2v;
    const size_t o0 = ((size_t)b * (K1v / 2) + c0 / 2) * N2v;
    for (int n = threadIdx.x; n < N2v; n += blockDim.x) {
        const int i0 = g_idx[base + n];
        const int i1 = g_idx[base + N2v + n];
        const int i2 = g_idx[base + 2 * N2v + n];
        const float w0 = g_wgt[base + n];
        const float w1 = g_wgt[base + N2v + n];
        const float w2 = g_wgt[base + 2 * N2v + n];
        float v[CPB];
        #pragma unroll
        for (int c = 0; c < CPB; c++)
            v[c] = sf[c][i0] * w0 + sf[c][i1] * w1 + sf[c][i2] * w2;
        uint32_t l01, l23;
        uint32_t h01 = pack_hi_lo(v[0], v[1], l01);
        uint32_t h23 = pack_hi_lo(v[2], v[3], l23);
        g_bh1[o0 + n] = h01;        g_bl1[o0 + n] = l01;
        g_bh1[o0 + N2v + n] = h23;  g_bl1[o0 + N2v + n] = l23;
    }
}

// ---------------- 2b) feat2 -> pair-packed B1 planes ----------------------------
__global__ void __launch_bounds__(256) f2cvt_kernel(const float* __restrict__ f2)
{
    const size_t gid = (size_t)blockIdx.x * 256 + threadIdx.x;
    const int n4 = (int)(gid & 2047);
    const int i = (int)((gid >> 11) & 63);
    const int b = (int)(gid >> 17);
    const float* r0 = f2 + ((size_t)b * C2v + 2 * i) * N2v + n4 * 4;
    float4 a = *(const float4*)r0;
    float4 c = *(const float4*)(r0 + N2v);
    uint32_t h[4], l[4];
    h[0] = pack_hi_lo(a.x, c.x, l[0]);
    h[1] = pack_hi_lo(a.y, c.y, l[1]);
    h[2] = pack_hi_lo(a.z, c.z, l[2]);
    h[3] = pack_hi_lo(a.w, c.w, l[3]);
    const size_t o = ((size_t)b * (K1v / 2) + 128 + i) * N2v + n4 * 4;
    *(uint4*)(g_bh1 + o) = make_uint4(h[0], h[1], h[2], h[3]);
    *(uint4*)(g_bl1 + o) = make_uint4(l[0], l[1], l[2], l[3]);
}

// ---------------- weight split ----------------
__global__ void wcvt_kernel(const float* __restrict__ src,
                            __nv_bfloat16* __restrict__ dh, __nv_bfloat16* __restrict__ dl)
{
    const size_t i4 = (size_t)blockIdx.x * 256 + threadIdx.x;
    float4 v = ((const float4*)src)[i4];
    uint32_t l01, l23;
    uint32_t h01 = pack_hi_lo(v.x, v.y, l01);
    uint32_t h23 = pack_hi_lo(v.z, v.w, l23);
    *(uint2*)(dh + i4 * 4) = make_uint2(h01, h23);
    *(uint2*)(dl + i4 * 4) = make_uint2(l01, l23);
}

// ---------------- BN1(finalize inline)+ReLU on y1 -> pair-packed B2 planes ------
__global__ void __launch_bounds__(256) bnsplit_kernel(
    const float* __restrict__ y1,
    const float* __restrict__ gs, const float* __restrict__ gq,
    const float* __restrict__ gamma, const float* __restrict__ beta)
{
    const size_t gid = (size_t)blockIdx.x * 256 + threadIdx.x;
    const int n4 = (int)(gid & 2047);
    const int i = (int)((gid >> 11) & 127);
    const int b = (int)(gid >> 18);
    const int c0 = 2 * i, c1 = 2 * i + 1;

    // block-local finalize: each block covers exactly one channel pair
    __shared__ float2 ssc[2];
    if (threadIdx.x < 2) {
        const int cc = 2 * i + threadIdx.x;
        ssc[threadIdx.x] = bn_fold(gs[cc], gq[cc], gamma[cc], beta[cc]);
    }
    __syncthreads();
    const float s0 = ssc[0].x, t0 = ssc[0].y, s1 = ssc[1].x, t1 = ssc[1].y;

    const float* r0 = y1 + ((size_t)b * COv + c0) * N2v + n4 * 4;
    float4 a = *(const float4*)r0;
    float4 c = *(const float4*)(r0 + N2v);
    a.x = fmaxf(fmaf(a.x, s0, t0), 0.f); a.y = fmaxf(fmaf(a.y, s0, t0), 0.f);
    a.z = fmaxf(fmaf(a.z, s0, t0), 0.f); a.w = fmaxf(fmaf(a.w, s0, t0), 0.f);
    c.x = fmaxf(fmaf(c.x, s1, t1), 0.f); c.y = fmaxf(fmaf(c.y, s1, t1), 0.f);
    c.z = fmaxf(fmaf(c.z, s1, t1), 0.f); c.w = fmaxf(fmaf(c.w, s1, t1), 0.f);
    uint32_t h[4], l[4];
    h[0] = pack_hi_lo(a.x, c.x, l[0]);
    h[1] = pack_hi_lo(a.y, c.y, l[1]);
    h[2] = pack_hi_lo(a.z, c.z, l[2]);
    h[3] = pack_hi_lo(a.w, c.w, l[3]);
    const size_t o = ((size_t)b * (COv / 2) + i) * N2v + n4 * 4;
    *(uint4*)(g_bh2 + o) = make_uint4(h[0], h[1], h[2], h[3]);
    *(uint4*)(g_bl2 + o) = make_uint4(l[0], l[1], l[2], l[3]);
}

// ---------------- final BN2(finalize inline)+ReLU in place on d_out -------------
__global__ void __launch_bounds__(256) bnapply_kernel(
    float* __restrict__ Y,
    const float* __restrict__ gs, const float* __restrict__ gq,
    const float* __restrict__ gamma, const float* __restrict__ beta)
{
    const size_t i = ((size_t)blockIdx.x * blockDim.x + threadIdx.x) * 4;
    const int c = (int)((i >> 13) & (COv - 1));
    // block covers 1024 contiguous elements -> single channel; thread 0 folds
    __shared__ float2 ssc;
    if (threadIdx.x == 0)
        ssc = bn_fold(gs[c], gq[c], gamma[c], beta[c]);
    __syncthreads();
    const float s = ssc.x, t = ssc.y;
    float4 v = *(float4*)(Y + i);
    v.x = fmaxf(fmaf(v.x, s, t), 0.f);
    v.y = fmaxf(fmaf(v.y, s, t), 0.f);
    v.z = fmaxf(fmaf(v.z, s, t), 0.f);
    v.w = fmaxf(fmaf(v.w, s, t), 0.f);
    *(float4*)(Y + i) = v;
}

// ---------------- launch ----------------
extern "C" void kernel_launch(void* const* d_in, const int* in_sizes, int n_in,
                              void* d_out, int out_size)
{
    const float* xyz2  = (const float*)d_in[0];
    const float* xyz1  = (const float*)d_in[1];
    const float* feat2 = (const float*)d_in[2];
    const float* feat1 = (const float*)d_in[3];
    const float* W1    = (const float*)d_in[4];
    const float* b1    = (const float*)d_in[5];
    const float* g1    = (const float*)d_in[6];
    const float* be1   = (const float*)d_in[7];
    const float* W2    = (const float*)d_in[8];
    const float* b2    = (const float*)d_in[9];
    const float* g2    = (const float*)d_in[10];
    const float* be2   = (const float*)d_in[11];
    float* out = (float*)d_out;

    float *y1, *s1, *q1, *s2, *q2;
    __nv_bfloat16 *ah1, *al1, *ah2, *al2;
    uint32_t *bh1, *bl1, *bh2, *bl2;
    cudaGetSymbolAddress((void**)&y1,  g_y1);
    cudaGetSymbolAddress((void**)&s1,  g_s1);
    cudaGetSymbolAddress((void**)&q1,  g_q1);
    cudaGetSymbolAddress((void**)&s2,  g_s2);
    cudaGetSymbolAddress((void**)&q2,  g_q2);
    cudaGetSymbolAddress((void**)&ah1, g_ah1);
    cudaGetSymbolAddress((void**)&al1, g_al1);
    cudaGetSymbolAddress((void**)&ah2, g_ah2);
    cudaGetSymbolAddress((void**)&al2, g_al2);
    cudaGetSymbolAddress((void**)&bh1, g_bh1);
    cudaGetSymbolAddress((void**)&bl1, g_bl1);
    cudaGetSymbolAddress((void**)&bh2, g_bh2);
    cudaGetSymbolAddress((void**)&bl2, g_bl2);

    cudaFuncSetAttribute(tgemm_kernel, cudaFuncAttributeMaxDynamicSharedMemorySize, SM_BYTES);

    wcvt_kernel<<<(COv * K1v) / 1024, 256>>>(W1, ah1, al1);
    wcvt_kernel<<<(COv * COv) / 1024, 256>>>(W2, ah2, al2);
    knn3_part_kernel<<<dim3(N2v / 256, BATCH, NSPLIT), 256>>>(xyz2, xyz1);
    knn3_merge_kernel<<<(BATCH * N2v) / 256, 256>>>(xyz2, xyz1);
    interp_kernel<<<dim3(C1v / CPB, BATCH), 256>>>(feat1);
    f2cvt_kernel<<<((size_t)BATCH * (C2v / 2) * (N2v / 4)) / 256, 256>>>(feat2);
    tgemm_kernel<<<dim3(N2v / BN, COv / BM, BATCH), 256, SM_BYTES>>>(
        ah1, al1, bh1, bl1, y1, K1v, b1, s1, q1);
    bnsplit_kernel<<<((size_t)BATCH * (COv / 2) * (N2v / 4)) / 256, 256>>>(y1, s1, q1, g1, be1);
    tgemm_kernel<<<dim3(N2v / BN, COv / BM, BATCH), 256, SM_BYTES>>>(
        ah2, al2, bh2, bl2, out, COv, b2, s2, q2);
    bnapply_kernel<<<((size_t)BATCH * COv * N2v) / 1024, 256>>>(out, s2, q2, g2, be2);
}